// round 4
// baseline (speedup 1.0000x reference)
#include <cuda_runtime.h>
#include <math.h>

#define TT 2048
#define BB 4
#define CCD 1024
#define QD 256
#define KVD 32
#define NPROJ 320           // 256 (q) + 32 (kd) + 32 (vd)
#define NROWS (BB*TT)       // 8192
#define VOCAB 50257

// ---------------- scratch (static device globals; no allocations) ----------------
__device__ float d_proj[NROWS * NPROJ];            // fused projection output
__device__ float d_kraw[NROWS * QD];
__device__ float d_vraw[NROWS * CCD];
__device__ float d_qf[NROWS * QD];
__device__ float d_kf[NROWS * QD];
__device__ float d_vf[NROWS * CCD];
__device__ float d_P[(size_t)BB * TT * TT];        // unnormalized exp(scores), 64 MB
__device__ float d_rowsum[NROWS];
__device__ int   d_idx32[NROWS];

// =====================================================================
// K0: normalize idx to int32, auto-detecting int32 vs int64 storage.
//     Detection reads only the first 128 bytes (safe for either dtype):
//     16 random int32 pairs interpreted as int64 are >= 2^32 w.p. ~1,
//     while genuine int64 indices are all in [0, VOCAB).
// =====================================================================
__global__ void idx_cvt_kernel(const void* __restrict__ raw) {
    const long long* p64 = (const long long*)raw;
    const int*       p32 = (const int*)raw;
    bool is64 = true;
    #pragma unroll
    for (int i = 0; i < 16; i++) {
        long long v = p64[i];
        if (v < 0 || v >= (long long)VOCAB) is64 = false;
    }
    int i = blockIdx.x * blockDim.x + threadIdx.x;
    if (i < NROWS) {
        int v = is64 ? (int)p64[i] : p32[i];
        // clamp defensively: never fault on a gather
        if (v < 0) v = 0;
        if (v >= VOCAB) v = VOCAB - 1;
        d_idx32[i] = v;
    }
}

// =====================================================================
// K1: fused projection GEMM  proj[r, n] = sum_c x[r,c] * W[n,c]
//     W rows: [0,256)=W_qq, [256,288)=W_k, [288,320)=W_v
//     64x64 tile, BK=32, 256 threads, 4x4 micro-tile
// =====================================================================
__global__ void proj_kernel(const float* __restrict__ x, const float* __restrict__ Wqq,
                            const float* __restrict__ Wk, const float* __restrict__ Wv) {
    __shared__ float As[32 * 68];
    __shared__ float Bs[32 * 68];
    const int tid = threadIdx.x;
    const int mb = blockIdx.x * 64;
    const int nb = blockIdx.y * 64;
    const int lr  = tid >> 2;         // loader row 0..63
    const int lc4 = (tid & 3) * 4;    // loader k offset
    const int tm = (tid >> 4) << 2;   // compute rows
    const int tn = (tid & 15) << 2;   // compute cols

    const float* arow = x + (size_t)(mb + lr) * CCD;
    const int nn = nb + lr;
    const float* wrow;
    if (nn < 256)      wrow = Wqq + (size_t)nn * CCD;
    else if (nn < 288) wrow = Wk  + (size_t)(nn - 256) * CCD;
    else               wrow = Wv  + (size_t)(nn - 288) * CCD;

    float acc[4][4] = {};
    for (int kt = 0; kt < CCD; kt += 32) {
        #pragma unroll
        for (int u = 0; u < 32; u += 16) {
            float4 a = *(const float4*)(arow + kt + lc4 + u);
            As[(lc4+u+0)*68+lr] = a.x; As[(lc4+u+1)*68+lr] = a.y;
            As[(lc4+u+2)*68+lr] = a.z; As[(lc4+u+3)*68+lr] = a.w;
            float4 b = *(const float4*)(wrow + kt + lc4 + u);
            Bs[(lc4+u+0)*68+lr] = b.x; Bs[(lc4+u+1)*68+lr] = b.y;
            Bs[(lc4+u+2)*68+lr] = b.z; Bs[(lc4+u+3)*68+lr] = b.w;
        }
        __syncthreads();
        #pragma unroll
        for (int k = 0; k < 32; k++) {
            float4 a = *(const float4*)&As[k*68 + tm];
            float4 b = *(const float4*)&Bs[k*68 + tn];
            acc[0][0] += a.x*b.x; acc[0][1] += a.x*b.y; acc[0][2] += a.x*b.z; acc[0][3] += a.x*b.w;
            acc[1][0] += a.y*b.x; acc[1][1] += a.y*b.y; acc[1][2] += a.y*b.z; acc[1][3] += a.y*b.w;
            acc[2][0] += a.z*b.x; acc[2][1] += a.z*b.y; acc[2][2] += a.z*b.z; acc[2][3] += a.z*b.w;
            acc[3][0] += a.w*b.x; acc[3][1] += a.w*b.y; acc[3][2] += a.w*b.z; acc[3][3] += a.w*b.w;
        }
        __syncthreads();
    }
    #pragma unroll
    for (int ii = 0; ii < 4; ii++) {
        float4 v = make_float4(acc[ii][0], acc[ii][1], acc[ii][2], acc[ii][3]);
        *(float4*)&d_proj[(size_t)(mb + tm + ii) * NPROJ + nb + tn] = v;
    }
}

// =====================================================================
// K2a: k_raw[r, o] = (kd[r,:] . W_kup[o,:]) * k_emb_tab[idx[r], o]
//      32 rows per block, 256 threads (one output column each)
// =====================================================================
__global__ void kup_kernel(const float* __restrict__ Wkup, const float* __restrict__ ktab) {
    __shared__ float Ws[32 * 257];     // transposed, padded: Ws[d*257+o]
    __shared__ float kds[32][32];
    const int tid = threadIdx.x;
    const int r0 = blockIdx.x * 32;
    for (int i2 = tid; i2 < QD * KVD; i2 += 256) {
        int o = i2 >> 5, d = i2 & 31;
        Ws[d * 257 + o] = Wkup[i2];
    }
    for (int i2 = tid; i2 < 32 * KVD; i2 += 256) {
        int rr = i2 >> 5, d = i2 & 31;
        kds[rr][d] = d_proj[(size_t)(r0 + rr) * NPROJ + 256 + d];
    }
    __syncthreads();
    float a[32];
    #pragma unroll
    for (int rr = 0; rr < 32; rr++) a[rr] = 0.f;
    #pragma unroll
    for (int d = 0; d < 32; d++) {
        float w = Ws[d * 257 + tid];
        #pragma unroll
        for (int rr = 0; rr < 32; rr++) a[rr] += kds[rr][d] * w;
    }
    #pragma unroll
    for (int rr = 0; rr < 32; rr++) {
        int ii = d_idx32[r0 + rr];
        d_kraw[(size_t)(r0 + rr) * QD + tid] = a[rr] * ktab[(size_t)ii * QD + tid];
    }
}

// =====================================================================
// K2b: v_raw[r, c] = tanh(vd[r,:] . W_vup[c,:]) * v_emb_tab[idx[r], c]
//      16 rows per block; W_vup streamed in 4 column chunks of 256
// =====================================================================
__global__ void vup_kernel(const float* __restrict__ Wvup, const float* __restrict__ vtab) {
    __shared__ float Wtc[32 * 257];    // transposed chunk: Wtc[d*257 + c_local]
    __shared__ float vds[16][32];
    const int tid = threadIdx.x;
    const int r0 = blockIdx.x * 16;
    for (int i2 = tid; i2 < 16 * KVD; i2 += 256) {
        int rr = i2 >> 5, d = i2 & 31;
        vds[rr][d] = d_proj[(size_t)(r0 + rr) * NPROJ + 288 + d];
    }
    for (int j = 0; j < 4; j++) {
        __syncthreads();  // protect Wtc reuse / vds ready
        for (int i2 = tid; i2 < 256 * KVD; i2 += 256) {
            int cl = i2 >> 5, d = i2 & 31;
            Wtc[d * 257 + cl] = Wvup[(size_t)(j * 256 + cl) * KVD + d];
        }
        __syncthreads();
        const int c = j * 256 + tid;
        float a[16];
        #pragma unroll
        for (int rr = 0; rr < 16; rr++) a[rr] = 0.f;
        #pragma unroll
        for (int d = 0; d < 32; d++) {
            float w = Wtc[d * 257 + tid];
            #pragma unroll
            for (int rr = 0; rr < 16; rr++) a[rr] += vds[rr][d] * w;
        }
        #pragma unroll
        for (int rr = 0; rr < 16; rr++) {
            int ii = d_idx32[r0 + rr];
            d_vraw[(size_t)(r0 + rr) * CCD + c] = tanhf(a[rr]) * vtab[(size_t)ii * CCD + c];
        }
    }
}

// =====================================================================
// K3: time-shift mix + LayerNorm. which: 0=q(proj slice), 1=k, 2=v
//     one block (256 thr) per row
// =====================================================================
__global__ void shift_ln_kernel(int which, const float* __restrict__ coef,
                                const float* __restrict__ g, const float* __restrict__ bta) {
    const float* raw; float* out; int stride, D;
    if (which == 0)      { raw = d_proj; out = d_qf; stride = NPROJ; D = QD;  }
    else if (which == 1) { raw = d_kraw; out = d_kf; stride = QD;    D = QD;  }
    else                 { raw = d_vraw; out = d_vf; stride = CCD;   D = CCD; }
    const int r = blockIdx.x;
    const int t = r & (TT - 1);
    const float* cur = raw + (size_t)r * stride;
    const float* prv = cur - stride;
    float y[4];
    float s = 0.f, s2 = 0.f;
    int cnt = 0;
    for (int d = threadIdx.x; d < D; d += 256) {
        float c = cur[d];
        float p = (t > 0) ? prv[d] : 0.f;
        float v = c + (p - c) * coef[d];
        y[cnt++] = v;
        s += v; s2 += v * v;
    }
    #pragma unroll
    for (int o = 16; o; o >>= 1) {
        s  += __shfl_xor_sync(0xffffffffu, s,  o);
        s2 += __shfl_xor_sync(0xffffffffu, s2, o);
    }
    __shared__ float ws[8], ws2[8];
    __shared__ float smean, srstd;
    if ((threadIdx.x & 31) == 0) { ws[threadIdx.x >> 5] = s; ws2[threadIdx.x >> 5] = s2; }
    __syncthreads();
    if (threadIdx.x == 0) {
        float S = 0.f, S2 = 0.f;
        #pragma unroll
        for (int i = 0; i < 8; i++) { S += ws[i]; S2 += ws2[i]; }
        float mean = S / D;
        float var  = S2 / D - mean * mean;
        smean = mean;
        srstd = rsqrtf(var + 1e-5f);
    }
    __syncthreads();
    cnt = 0;
    for (int d = threadIdx.x; d < D; d += 256) {
        out[(size_t)r * D + d] = (y[cnt++] - smean) * srstd * g[d] + bta[d];
    }
}

// =====================================================================
// K4a: unnormalized attention weights.
//   P[b,t,s] = exp(64*tanh(q.k/1024)) for s<=t (0 above diag in diag tile)
//   64x64 tile per block over lower triangle; K-dim 256 in chunks of 64
// =====================================================================
__global__ void score_kernel() {
    __shared__ float Qs[64 * 68];
    __shared__ float Ks[64 * 68];
    const int j = blockIdx.x, i = blockIdx.y, b = blockIdx.z;
    if (j > i) return;                       // upper triangle: nothing
    const int tid = threadIdx.x;
    const int lr  = tid >> 2;
    const int lc4 = (tid & 3) * 4;
    const int tm = (tid >> 4) << 2;
    const int tn = (tid & 15) << 2;
    const float* qrow = d_qf + (size_t)(b * TT + i * 64 + lr) * QD;
    const float* krow = d_kf + (size_t)(b * TT + j * 64 + lr) * QD;
    float acc[4][4] = {};
    for (int kt = 0; kt < QD; kt += 64) {
        #pragma unroll
        for (int u = 0; u < 64; u += 16) {
            float4 a = *(const float4*)(qrow + kt + lc4 + u);
            Qs[(lc4+u+0)*68+lr] = a.x; Qs[(lc4+u+1)*68+lr] = a.y;
            Qs[(lc4+u+2)*68+lr] = a.z; Qs[(lc4+u+3)*68+lr] = a.w;
            float4 kk = *(const float4*)(krow + kt + lc4 + u);
            Ks[(lc4+u+0)*68+lr] = kk.x; Ks[(lc4+u+1)*68+lr] = kk.y;
            Ks[(lc4+u+2)*68+lr] = kk.z; Ks[(lc4+u+3)*68+lr] = kk.w;
        }
        __syncthreads();
        #pragma unroll
        for (int k = 0; k < 64; k++) {
            float4 a = *(const float4*)&Qs[k*68 + tm];
            float4 c = *(const float4*)&Ks[k*68 + tn];
            acc[0][0] += a.x*c.x; acc[0][1] += a.x*c.y; acc[0][2] += a.x*c.z; acc[0][3] += a.x*c.w;
            acc[1][0] += a.y*c.x; acc[1][1] += a.y*c.y; acc[1][2] += a.y*c.z; acc[1][3] += a.y*c.w;
            acc[2][0] += a.z*c.x; acc[2][1] += a.z*c.y; acc[2][2] += a.z*c.z; acc[2][3] += a.z*c.w;
            acc[3][0] += a.w*c.x; acc[3][1] += a.w*c.y; acc[3][2] += a.w*c.z; acc[3][3] += a.w*c.w;
        }
        __syncthreads();
    }
    const float inv1024 = 1.0f / 1024.0f;
    #pragma unroll
    for (int ii = 0; ii < 4; ii++) {
        const int rrow = i * 64 + tm + ii;
        float4 pv;
        float* pp = (float*)&pv;
        #pragma unroll
        for (int jj = 0; jj < 4; jj++) {
            const int ccol = j * 64 + tn + jj;
            float sc = 64.0f * tanhf(acc[ii][jj] * inv1024);
            pp[jj] = (ccol <= rrow) ? expf(sc) : 0.0f;   // exp(64) ~ 6e27: safe in fp32
        }
        *(float4*)&d_P[(size_t)(b * TT + rrow) * TT + j * 64 + tn] = pv;
    }
}

// K4c: softmax denominators (deterministic, no atomics)
__global__ void rowsum_kernel() {
    const int r = blockIdx.x;
    const int t = r & (TT - 1);
    const float* row = d_P + (size_t)r * TT;
    float s = 0.f;
    for (int j = threadIdx.x; j <= t; j += 256) s += row[j];
    #pragma unroll
    for (int o = 16; o; o >>= 1) s += __shfl_xor_sync(0xffffffffu, s, o);
    __shared__ float ws[8];
    if ((threadIdx.x & 31) == 0) ws[threadIdx.x >> 5] = s;
    __syncthreads();
    if (threadIdx.x == 0) {
        float tot = 0.f;
        #pragma unroll
        for (int i = 0; i < 8; i++) tot += ws[i];
        d_rowsum[r] = tot;
    }
}

// =====================================================================
// K4b: out = (P @ V) / rowsum.  64(q) x 64(c) tile, BK=32, causal K range
// =====================================================================
__global__ void pv_kernel(float* __restrict__ out) {
    __shared__ float Ps[32 * 68];
    __shared__ float Vs[32 * 68];
    const int tid = threadIdx.x;
    const int cb = blockIdx.x * 64;
    const int ib = blockIdx.y;
    const int b  = blockIdx.z;
    const int row0 = ib * 64;
    const int tm = (tid >> 4) << 2;
    const int tn = (tid & 15) << 2;
    const int plr  = tid >> 2;
    const int plc4 = (tid & 3) * 4;
    const int vk = tid >> 3;
    const int vn = (tid & 7) * 8;
    const float* prow = d_P + (size_t)(b * TT + row0 + plr) * TT;
    float acc[4][4] = {};
    const int kend = row0 + 64;          // causal: keys in [0, (ib+1)*64)
    for (int k0 = 0; k0 < kend; k0 += 32) {
        #pragma unroll
        for (int u = 0; u < 32; u += 16) {
            float4 p = *(const float4*)(prow + k0 + plc4 + u);
            Ps[(plc4+u+0)*68+plr] = p.x; Ps[(plc4+u+1)*68+plr] = p.y;
            Ps[(plc4+u+2)*68+plr] = p.z; Ps[(plc4+u+3)*68+plr] = p.w;
        }
        const float* vrow = d_vf + (size_t)(b * TT + k0 + vk) * CCD + cb;
        *(float4*)&Vs[vk*68 + vn]     = *(const float4*)(vrow + vn);
        *(float4*)&Vs[vk*68 + vn + 4] = *(const float4*)(vrow + vn + 4);
        __syncthreads();
        #pragma unroll
        for (int k = 0; k < 32; k++) {
            float4 a = *(const float4*)&Ps[k*68 + tm];
            float4 v = *(const float4*)&Vs[k*68 + tn];
            acc[0][0] += a.x*v.x; acc[0][1] += a.x*v.y; acc[0][2] += a.x*v.z; acc[0][3] += a.x*v.w;
            acc[1][0] += a.y*v.x; acc[1][1] += a.y*v.y; acc[1][2] += a.y*v.z; acc[1][3] += a.y*v.w;
            acc[2][0] += a.z*v.x; acc[2][1] += a.z*v.y; acc[2][2] += a.z*v.z; acc[2][3] += a.z*v.w;
            acc[3][0] += a.w*v.x; acc[3][1] += a.w*v.y; acc[3][2] += a.w*v.z; acc[3][3] += a.w*v.w;
        }
        __syncthreads();
    }
    #pragma unroll
    for (int ii = 0; ii < 4; ii++) {
        const int r = b * TT + row0 + tm + ii;
        const float inv = 1.0f / d_rowsum[r];
        float4 o4 = make_float4(acc[ii][0]*inv, acc[ii][1]*inv, acc[ii][2]*inv, acc[ii][3]*inv);
        *(float4*)&out[(size_t)r * CCD + cb + tn] = o4;
    }
}

// =====================================================================
extern "C" void kernel_launch(void* const* d_in, const int* in_sizes, int n_in,
                              void* d_out, int out_size) {
    const float*     x     = (const float*)d_in[0];
    const void*      idx   = d_in[1];                 // int32 or int64; auto-detected
    const float*     Wqq   = (const float*)d_in[2];
    const float*     Wk    = (const float*)d_in[3];
    const float*     Wkup  = (const float*)d_in[4];
    const float*     Wv    = (const float*)d_in[5];
    const float*     Wvup  = (const float*)d_in[6];
    const float*     ktab  = (const float*)d_in[7];
    const float*     vtab  = (const float*)d_in[8];
    const float*     xq    = (const float*)d_in[9];
    const float*     xk    = (const float*)d_in[10];
    const float*     xv    = (const float*)d_in[11];
    const float*     gq    = (const float*)d_in[12];
    const float*     bq    = (const float*)d_in[13];
    const float*     gk    = (const float*)d_in[14];
    const float*     bk    = (const float*)d_in[15];
    const float*     gv    = (const float*)d_in[16];
    const float*     bv    = (const float*)d_in[17];
    float* out = (float*)d_out;

    idx_cvt_kernel<<<NROWS / 256, 256>>>(idx);
    proj_kernel<<<dim3(128, 5), 256>>>(x, Wqq, Wk, Wv);
    kup_kernel<<<NROWS / 32, 256>>>(Wkup, ktab);
    vup_kernel<<<NROWS / 16, 256>>>(Wvup, vtab);
    shift_ln_kernel<<<NROWS, 256>>>(0, xq, gq, bq);
    shift_ln_kernel<<<NROWS, 256>>>(1, xk, gk, bk);
    shift_ln_kernel<<<NROWS, 256>>>(2, xv, gv, bv);
    score_kernel<<<dim3(32, 32, 4), 256>>>();
    rowsum_kernel<<<NROWS, 256>>>();
    pv_kernel<<<dim3(16, 32, 4), 256>>>(out);
}

// round 6
// speedup vs baseline: 1.4007x; 1.4007x over previous
#include <cuda_runtime.h>
#include <cuda_bf16.h>
#include <math.h>
#include <stdint.h>

#define TT 2048
#define BB 4
#define CCD 1024
#define QD 256
#define KVD 32
#define NPROJ 320
#define NROWS (BB*TT)       // 8192
#define VOCAB 50257

// ---------------- scratch (static device globals; no allocations) ----------------
__device__ __align__(16) float d_proj[NROWS * NPROJ];
__device__ __align__(16) float d_kraw[NROWS * QD];
__device__ __align__(16) float d_vraw[NROWS * CCD];
__device__ __align__(16) float d_vf[NROWS * CCD];
__device__ __align__(16) __nv_bfloat16 d_qh[NROWS * QD];
__device__ __align__(16) __nv_bfloat16 d_ql[NROWS * QD];
__device__ __align__(16) __nv_bfloat16 d_kh[NROWS * QD];
__device__ __align__(16) __nv_bfloat16 d_kl[NROWS * QD];
__device__ __align__(16) __nv_bfloat16 d_vth[(size_t)NROWS * CCD];  // [b][c][t]
__device__ __align__(16) __nv_bfloat16 d_vtl[(size_t)NROWS * CCD];
__device__ __align__(16) __nv_bfloat16 d_ph[(size_t)BB * TT * TT];  // P hi, [b][t][s]
__device__ __align__(16) __nv_bfloat16 d_pl[(size_t)BB * TT * TT];  // P lo
__device__ float d_psum[(size_t)NROWS * 64];    // per-row, per-32-col-stripe partials
__device__ float d_rowsum[NROWS];
__device__ int   d_idx32[NROWS];

// ---------------- warp-mma helpers (sm_80-class, legal on base sm_103) ----------------
__device__ __forceinline__ uint32_t smem_to_u32(const void* p) {
    uint32_t a;
    asm("{ .reg .u64 t; cvta.to.shared.u64 t, %1; cvt.u32.u64 %0, t; }" : "=r"(a) : "l"(p));
    return a;
}
__device__ __forceinline__ void ldsm4(uint32_t r[4], uint32_t a) {
    asm volatile("ldmatrix.sync.aligned.m8n8.x4.shared.b16 {%0,%1,%2,%3}, [%4];"
                 : "=r"(r[0]), "=r"(r[1]), "=r"(r[2]), "=r"(r[3]) : "r"(a));
}
__device__ __forceinline__ void ldsm2(uint32_t r[2], uint32_t a) {
    asm volatile("ldmatrix.sync.aligned.m8n8.x2.shared.b16 {%0,%1}, [%2];"
                 : "=r"(r[0]), "=r"(r[1]) : "r"(a));
}
__device__ __forceinline__ void mma_bf16(float c[4], const uint32_t a[4], const uint32_t b[2]) {
    asm volatile("mma.sync.aligned.m16n8k16.row.col.f32.bf16.bf16.f32 "
                 "{%0,%1,%2,%3}, {%4,%5,%6,%7}, {%8,%9}, {%0,%1,%2,%3};"
                 : "+f"(c[0]), "+f"(c[1]), "+f"(c[2]), "+f"(c[3])
                 : "r"(a[0]), "r"(a[1]), "r"(a[2]), "r"(a[3]), "r"(b[0]), "r"(b[1]));
}
// pack two fp32 into bf16x2 (lo word = first arg)
__device__ __forceinline__ uint32_t pack_bf16x2(float lo, float hi) {
    uint32_t r;
    asm("cvt.rn.bf16x2.f32 %0, %1, %2;" : "=r"(r) : "f"(hi), "f"(lo));
    return r;
}

// smem tile offsets (bytes). 128 rows x 40 bf16 (80B stride, 16B aligned)
#define SQH 0
#define SQL 10240
#define SKH 20480
#define SKL 30720
#define DYN_SMEM 40960

// =====================================================================
// K0: idx normalize (int32/int64 auto-detect)
// =====================================================================
__global__ void idx_cvt_kernel(const void* __restrict__ raw) {
    const long long* p64 = (const long long*)raw;
    const int*       p32 = (const int*)raw;
    bool is64 = true;
    #pragma unroll
    for (int i = 0; i < 16; i++) {
        long long v = p64[i];
        if (v < 0 || v >= (long long)VOCAB) is64 = false;
    }
    int i = blockIdx.x * blockDim.x + threadIdx.x;
    if (i < NROWS) {
        int v = is64 ? (int)p64[i] : p32[i];
        if (v < 0) v = 0;
        if (v >= VOCAB) v = VOCAB - 1;
        d_idx32[i] = v;
    }
}

// =====================================================================
// K1: fused projection GEMM (fp32 SIMT)
// =====================================================================
__global__ void proj_kernel(const float* __restrict__ x, const float* __restrict__ Wqq,
                            const float* __restrict__ Wk, const float* __restrict__ Wv) {
    __shared__ float As[32 * 68];
    __shared__ float Bs[32 * 68];
    const int tid = threadIdx.x;
    const int mb = blockIdx.x * 64;
    const int nb = blockIdx.y * 64;
    const int lr  = tid >> 2;
    const int lc4 = (tid & 3) * 4;
    const int tm = (tid >> 4) << 2;
    const int tn = (tid & 15) << 2;

    const float* arow = x + (size_t)(mb + lr) * CCD;
    const int nn = nb + lr;
    const float* wrow;
    if (nn < 256)      wrow = Wqq + (size_t)nn * CCD;
    else if (nn < 288) wrow = Wk  + (size_t)(nn - 256) * CCD;
    else               wrow = Wv  + (size_t)(nn - 288) * CCD;

    float acc[4][4] = {};
    for (int kt = 0; kt < CCD; kt += 32) {
        #pragma unroll
        for (int u = 0; u < 32; u += 16) {
            float4 a = *(const float4*)(arow + kt + lc4 + u);
            As[(lc4+u+0)*68+lr] = a.x; As[(lc4+u+1)*68+lr] = a.y;
            As[(lc4+u+2)*68+lr] = a.z; As[(lc4+u+3)*68+lr] = a.w;
            float4 b = *(const float4*)(wrow + kt + lc4 + u);
            Bs[(lc4+u+0)*68+lr] = b.x; Bs[(lc4+u+1)*68+lr] = b.y;
            Bs[(lc4+u+2)*68+lr] = b.z; Bs[(lc4+u+3)*68+lr] = b.w;
        }
        __syncthreads();
        #pragma unroll
        for (int k = 0; k < 32; k++) {
            float4 a = *(const float4*)&As[k*68 + tm];
            float4 b = *(const float4*)&Bs[k*68 + tn];
            acc[0][0] += a.x*b.x; acc[0][1] += a.x*b.y; acc[0][2] += a.x*b.z; acc[0][3] += a.x*b.w;
            acc[1][0] += a.y*b.x; acc[1][1] += a.y*b.y; acc[1][2] += a.y*b.z; acc[1][3] += a.y*b.w;
            acc[2][0] += a.z*b.x; acc[2][1] += a.z*b.y; acc[2][2] += a.z*b.z; acc[2][3] += a.z*b.w;
            acc[3][0] += a.w*b.x; acc[3][1] += a.w*b.y; acc[3][2] += a.w*b.z; acc[3][3] += a.w*b.w;
        }
        __syncthreads();
    }
    #pragma unroll
    for (int ii = 0; ii < 4; ii++) {
        float4 v = make_float4(acc[ii][0], acc[ii][1], acc[ii][2], acc[ii][3]);
        *(float4*)&d_proj[(size_t)(mb + tm + ii) * NPROJ + nb + tn] = v;
    }
}

// =====================================================================
// K2a/K2b: low-rank up-projections
// =====================================================================
__global__ void kup_kernel(const float* __restrict__ Wkup, const float* __restrict__ ktab) {
    __shared__ float Ws[32 * 257];
    __shared__ float kds[32][32];
    const int tid = threadIdx.x;
    const int r0 = blockIdx.x * 32;
    for (int i2 = tid; i2 < QD * KVD; i2 += 256) {
        int o = i2 >> 5, d = i2 & 31;
        Ws[d * 257 + o] = Wkup[i2];
    }
    for (int i2 = tid; i2 < 32 * KVD; i2 += 256) {
        int rr = i2 >> 5, d = i2 & 31;
        kds[rr][d] = d_proj[(size_t)(r0 + rr) * NPROJ + 256 + d];
    }
    __syncthreads();
    float a[32];
    #pragma unroll
    for (int rr = 0; rr < 32; rr++) a[rr] = 0.f;
    #pragma unroll
    for (int d = 0; d < 32; d++) {
        float w = Ws[d * 257 + tid];
        #pragma unroll
        for (int rr = 0; rr < 32; rr++) a[rr] += kds[rr][d] * w;
    }
    #pragma unroll
    for (int rr = 0; rr < 32; rr++) {
        int ii = d_idx32[r0 + rr];
        d_kraw[(size_t)(r0 + rr) * QD + tid] = a[rr] * ktab[(size_t)ii * QD + tid];
    }
}

__global__ void vup_kernel(const float* __restrict__ Wvup, const float* __restrict__ vtab) {
    __shared__ float Wtc[32 * 257];
    __shared__ float vds[16][32];
    const int tid = threadIdx.x;
    const int r0 = blockIdx.x * 16;
    for (int i2 = tid; i2 < 16 * KVD; i2 += 256) {
        int rr = i2 >> 5, d = i2 & 31;
        vds[rr][d] = d_proj[(size_t)(r0 + rr) * NPROJ + 288 + d];
    }
    for (int j = 0; j < 4; j++) {
        __syncthreads();
        for (int i2 = tid; i2 < 256 * KVD; i2 += 256) {
            int cl = i2 >> 5, d = i2 & 31;
            Wtc[d * 257 + cl] = Wvup[(size_t)(j * 256 + cl) * KVD + d];
        }
        __syncthreads();
        const int c = j * 256 + tid;
        float a[16];
        #pragma unroll
        for (int rr = 0; rr < 16; rr++) a[rr] = 0.f;
        #pragma unroll
        for (int d = 0; d < 32; d++) {
            float w = Wtc[d * 257 + tid];
            #pragma unroll
            for (int rr = 0; rr < 16; rr++) a[rr] += vds[rr][d] * w;
        }
        #pragma unroll
        for (int rr = 0; rr < 16; rr++) {
            int ii = d_idx32[r0 + rr];
            d_vraw[(size_t)(r0 + rr) * CCD + c] = tanhf(a[rr]) * vtab[(size_t)ii * CCD + c];
        }
    }
}

// =====================================================================
// K3: time-shift + LayerNorm; q/k emit bf16 hi/lo, v emits fp32
// =====================================================================
__global__ void shift_ln_kernel(int which, const float* __restrict__ coef,
                                const float* __restrict__ g, const float* __restrict__ bta) {
    const float* raw; int stride, D;
    float* outf = nullptr; __nv_bfloat16 *oh = nullptr, *ol = nullptr;
    if (which == 0)      { raw = d_proj; stride = NPROJ; D = QD;  oh = d_qh; ol = d_ql; }
    else if (which == 1) { raw = d_kraw; stride = QD;    D = QD;  oh = d_kh; ol = d_kl; }
    else                 { raw = d_vraw; stride = CCD;   D = CCD; outf = d_vf; }
    const int r = blockIdx.x;
    const int t = r & (TT - 1);
    const float* cur = raw + (size_t)r * stride;
    const float* prv = cur - stride;
    float y[4];
    float s = 0.f, s2 = 0.f;
    int cnt = 0;
    for (int d = threadIdx.x; d < D; d += 256) {
        float c = cur[d];
        float p = (t > 0) ? prv[d] : 0.f;
        float v = c + (p - c) * coef[d];
        y[cnt++] = v;
        s += v; s2 += v * v;
    }
    #pragma unroll
    for (int o = 16; o; o >>= 1) {
        s  += __shfl_xor_sync(0xffffffffu, s,  o);
        s2 += __shfl_xor_sync(0xffffffffu, s2, o);
    }
    __shared__ float ws[8], ws2[8];
    __shared__ float smean, srstd;
    if ((threadIdx.x & 31) == 0) { ws[threadIdx.x >> 5] = s; ws2[threadIdx.x >> 5] = s2; }
    __syncthreads();
    if (threadIdx.x == 0) {
        float S = 0.f, S2 = 0.f;
        #pragma unroll
        for (int i = 0; i < 8; i++) { S += ws[i]; S2 += ws2[i]; }
        float mean = S / D;
        float var  = S2 / D - mean * mean;
        smean = mean;
        srstd = rsqrtf(var + 1e-5f);
    }
    __syncthreads();
    cnt = 0;
    for (int d = threadIdx.x; d < D; d += 256) {
        float o = (y[cnt++] - smean) * srstd * g[d] + bta[d];
        if (which == 2) {
            outf[(size_t)r * D + d] = o;
        } else {
            __nv_bfloat16 hi = __float2bfloat16(o);
            oh[(size_t)r * D + d] = hi;
            ol[(size_t)r * D + d] = __float2bfloat16(o - __bfloat162float(hi));
        }
    }
}

// =====================================================================
// K3b: transpose V -> Vt[b][c][t], split bf16 hi/lo
// =====================================================================
__global__ void vt_cvt_kernel() {
    __shared__ float ts[32][33];
    const int c0 = blockIdx.x * 32;
    const int r0 = blockIdx.y * 32;
    const int lx = threadIdx.x & 31;
    const int ly = threadIdx.x >> 5;
    #pragma unroll
    for (int i = 0; i < 4; i++) {
        int rr = ly + i * 8;
        ts[rr][lx] = d_vf[(size_t)(r0 + rr) * CCD + c0 + lx];
    }
    __syncthreads();
    const int bz = r0 >> 11;
    const int t0 = r0 & (TT - 1);
    #pragma unroll
    for (int i = 0; i < 4; i++) {
        int cc = ly + i * 8;
        float v = ts[lx][cc];
        size_t o = (size_t)(bz * CCD + c0 + cc) * TT + t0 + lx;
        __nv_bfloat16 hi = __float2bfloat16(v);
        d_vth[o] = hi;
        d_vtl[o] = __float2bfloat16(v - __bfloat162float(hi));
    }
}

// =====================================================================
// K4a: score via mma.sync. CTA 128x128, 8 warps (2m x 4n), warp 64x32.
//   3-term bf16 hi/lo => fp32-class accuracy. Epilogue: exact tanh/exp,
//   causal mask, P hi/lo store (smem-staged), per-stripe row partials.
// =====================================================================
__global__ void __launch_bounds__(256) score_mma_kernel() {
    extern __shared__ char smem[];
    const int tj = blockIdx.x, ti = blockIdx.y, b = blockIdx.z;
    if (tj > ti) return;
    const uint32_t sb = smem_to_u32(smem);
    const int tid  = threadIdx.x;
    const int lane = tid & 31;
    const int wid  = tid >> 5;
    const int wm = wid & 1;          // 2 warp-rows (64 each)
    const int wn = wid >> 1;         // 4 warp-cols (32 each)
    const int g = lane >> 2, q = lane & 3;

    float acc[4][4][4] = {};

    const int lrow = tid >> 1;       // loader row
    const int lh   = tid & 1;        // loader k-half (16 bf16)
    const size_t qrow = (size_t)(b * TT + ti * 128 + lrow) * QD;
    const size_t krow = (size_t)(b * TT + tj * 128 + lrow) * QD;
    const uint32_t sdst = lrow * 80 + lh * 32;

    for (int k0 = 0; k0 < QD; k0 += 32) {
        {
            const uint4* gq_h = (const uint4*)(d_qh + qrow + k0 + lh * 16);
            const uint4* gq_l = (const uint4*)(d_ql + qrow + k0 + lh * 16);
            const uint4* gk_h = (const uint4*)(d_kh + krow + k0 + lh * 16);
            const uint4* gk_l = (const uint4*)(d_kl + krow + k0 + lh * 16);
            *(uint4*)(smem + SQH + sdst)      = gq_h[0];
            *(uint4*)(smem + SQH + sdst + 16) = gq_h[1];
            *(uint4*)(smem + SQL + sdst)      = gq_l[0];
            *(uint4*)(smem + SQL + sdst + 16) = gq_l[1];
            *(uint4*)(smem + SKH + sdst)      = gk_h[0];
            *(uint4*)(smem + SKH + sdst + 16) = gk_h[1];
            *(uint4*)(smem + SKL + sdst)      = gk_l[0];
            *(uint4*)(smem + SKL + sdst + 16) = gk_l[1];
        }
        __syncthreads();
        #pragma unroll
        for (int k16 = 0; k16 < 2; k16++) {
            const int kc = k16 * 16;
            uint32_t bh[4][2], bl[4][2];
            const int brow = lane & 7;
            const int bcol = kc + ((lane >> 3) & 1) * 8;
            #pragma unroll
            for (int ni = 0; ni < 4; ni++) {
                uint32_t boff = (wn * 32 + ni * 8 + brow) * 80 + bcol * 2;
                ldsm2(bh[ni], sb + SKH + boff);
                ldsm2(bl[ni], sb + SKL + boff);
            }
            const int arow = wm * 64 + (lane & 15);
            const int acol = kc + (lane >> 4) * 8;
            #pragma unroll
            for (int mi = 0; mi < 4; mi++) {
                uint32_t ah[4], al[4];
                uint32_t aoff = (arow + mi * 16) * 80 + acol * 2;
                ldsm4(ah, sb + SQH + aoff);
                ldsm4(al, sb + SQL + aoff);
                #pragma unroll
                for (int ni = 0; ni < 4; ni++) {
                    mma_bf16(acc[mi][ni], ah, bh[ni]);
                    mma_bf16(acc[mi][ni], ah, bl[ni]);
                    mma_bf16(acc[mi][ni], al, bh[ni]);
                }
            }
        }
        __syncthreads();
    }

    // ---- transform: p = exp(64*tanh(d/1024)), mask, row partials ----
    #pragma unroll
    for (int mi = 0; mi < 4; mi++) {
        const int tg0 = ti * 128 + wm * 64 + mi * 16 + g;
        const int tg1 = tg0 + 8;
        float ps0 = 0.f, ps1 = 0.f;
        #pragma unroll
        for (int ni = 0; ni < 4; ni++) {
            const int sg = tj * 128 + wn * 32 + ni * 8 + q * 2;
            #pragma unroll
            for (int e = 0; e < 4; e++) {
                const int col = sg + (e & 1);
                const int row = (e < 2) ? tg0 : tg1;
                float p = 0.f;
                if (col <= row) {
                    float d = acc[mi][ni][e];
                    float u = __expf(d * (1.f / 512.f));          // e^{2x}
                    float th = __fdividef(u - 1.f, u + 1.f);      // tanh(x)
                    p = __expf(64.f * th);
                }
                acc[mi][ni][e] = p;
                if (e < 2) ps0 += p; else ps1 += p;
            }
        }
        ps0 += __shfl_xor_sync(0xffffffffu, ps0, 1);
        ps0 += __shfl_xor_sync(0xffffffffu, ps0, 2);
        ps1 += __shfl_xor_sync(0xffffffffu, ps1, 1);
        ps1 += __shfl_xor_sync(0xffffffffu, ps1, 2);
        if (q == 0) {
            d_psum[(size_t)(b * TT + tg0) * 64 + tj * 4 + wn] = ps0;
            d_psum[(size_t)(b * TT + tg1) * 64 + tj * 4 + wn] = ps1;
        }
    }

    // ---- stage + store P hi, then P lo (coalesced 128B rows) ----
    uint32_t* stg = (uint32_t*)smem;          // [128][68] u32
    const int cpair = wn * 16 + q;            // + ni*4
    for (int pass = 0; pass < 2; pass++) {
        __syncthreads();
        #pragma unroll
        for (int mi = 0; mi < 4; mi++) {
            const int r0 = wm * 64 + mi * 16 + g;
            #pragma unroll
            for (int ni = 0; ni < 4; ni++) {
                float v0 = acc[mi][ni][0], v1 = acc[mi][ni][1];
                float v2 = acc[mi][ni][2], v3 = acc[mi][ni][3];
                if (pass == 1) {
                    v0 -= __bfloat162float(__float2bfloat16(v0));
                    v1 -= __bfloat162float(__float2bfloat16(v1));
                    v2 -= __bfloat162float(__float2bfloat16(v2));
                    v3 -= __bfloat162float(__float2bfloat16(v3));
                    // pass-1 writes lo = p - bf16(p); pass-0 wrote bf16(p)
                }
                stg[r0 * 68 + cpair + ni * 4]       = pack_bf16x2(v0, v1);
                stg[(r0 + 8) * 68 + cpair + ni * 4] = pack_bf16x2(v2, v3);
            }
        }
        __syncthreads();
        __nv_bfloat16* gbase = (pass == 0) ? d_ph : d_pl;
        const int srow = tid >> 1;
        const int c0 = (tid & 1) * 32;
        uint4* gp = (uint4*)(gbase + (size_t)(b * TT + ti * 128 + srow) * TT
                             + (size_t)tj * 128 + (tid & 1) * 64);
        const uint4* sp = (const uint4*)(stg + srow * 68 + c0);
        #pragma unroll
        for (int i = 0; i < 8; i++) gp[i] = sp[i];
    }
}

// =====================================================================
// K4c: rowsum from 32-col stripe partials
// =====================================================================
__global__ void psum_reduce_kernel() {
    int r = blockIdx.x * 256 + threadIdx.x;
    int t = r & (TT - 1);
    int n = (t >> 5) + 1;
    const float* p = d_psum + (size_t)r * 64;
    float s = 0.f;
    for (int j = 0; j < n; j++) s += p[j];
    d_rowsum[r] = s;
}

// =====================================================================
// K4b: PV via mma.sync. out tile 128(t) x 128(c); A=P hi/lo, B=Vt hi/lo.
// =====================================================================
__global__ void __launch_bounds__(256) pv_mma_kernel(float* __restrict__ out) {
    extern __shared__ char smem[];
    const int cb = blockIdx.x, ti = blockIdx.y, b = blockIdx.z;
    const uint32_t sb = smem_to_u32(smem);
    const int tid  = threadIdx.x;
    const int lane = tid & 31;
    const int wid  = tid >> 5;
    const int wm = wid & 1;
    const int wn = wid >> 1;
    const int g = lane >> 2, q = lane & 3;

    float acc[4][4][4] = {};

    const int lrow = tid >> 1;
    const int lh   = tid & 1;
    const size_t prow = (size_t)(b * TT + ti * 128 + lrow) * TT;
    const size_t vrow = (size_t)(b * CCD + cb * 128 + lrow) * TT;
    const uint32_t sdst = lrow * 80 + lh * 32;

    const int kend = (ti + 1) * 128;
    for (int k0 = 0; k0 < kend; k0 += 32) {
        {
            const uint4* ga_h = (const uint4*)(d_ph + prow + k0 + lh * 16);
            const uint4* ga_l = (const uint4*)(d_pl + prow + k0 + lh * 16);
            const uint4* gb_h = (const uint4*)(d_vth + vrow + k0 + lh * 16);
            const uint4* gb_l = (const uint4*)(d_vtl + vrow + k0 + lh * 16);
            *(uint4*)(smem + SQH + sdst)      = ga_h[0];
            *(uint4*)(smem + SQH + sdst + 16) = ga_h[1];
            *(uint4*)(smem + SQL + sdst)      = ga_l[0];
            *(uint4*)(smem + SQL + sdst + 16) = ga_l[1];
            *(uint4*)(smem + SKH + sdst)      = gb_h[0];
            *(uint4*)(smem + SKH + sdst + 16) = gb_h[1];
            *(uint4*)(smem + SKL + sdst)      = gb_l[0];
            *(uint4*)(smem + SKL + sdst + 16) = gb_l[1];
        }
        __syncthreads();
        #pragma unroll
        for (int k16 = 0; k16 < 2; k16++) {
            const int kc = k16 * 16;
            uint32_t bh[4][2], bl[4][2];
            const int brow = lane & 7;
            const int bcol = kc + ((lane >> 3) & 1) * 8;
            #pragma unroll
            for (int ni = 0; ni < 4; ni++) {
                uint32_t boff = (wn * 32 + ni * 8 + brow) * 80 + bcol * 2;
                ldsm2(bh[ni], sb + SKH + boff);
                ldsm2(bl[ni], sb + SKL + boff);
            }
            const int arow = wm * 64 + (lane & 15);
            const int acol = kc + (lane >> 4) * 8;
            #pragma unroll
            for (int mi = 0; mi < 4; mi++) {
                uint32_t ah[4], al[4];
                uint32_t aoff = (arow + mi * 16) * 80 + acol * 2;
                ldsm4(ah, sb + SQH + aoff);
                ldsm4(al, sb + SQL + aoff);
                #pragma unroll
                for (int ni = 0; ni < 4; ni++) {
                    mma_bf16(acc[mi][ni], ah, bh[ni]);
                    mma_bf16(acc[mi][ni], ah, bl[ni]);
                    mma_bf16(acc[mi][ni], al, bh[ni]);
                }
            }
        }
        __syncthreads();
    }

    // normalization factors for this thread's 8 rows
    float inv0[4], inv1[4];
    #pragma unroll
    for (int mi = 0; mi < 4; mi++) {
        int rg = b * TT + ti * 128 + wm * 64 + mi * 16 + g;
        inv0[mi] = 1.f / d_rowsum[rg];
        inv1[mi] = 1.f / d_rowsum[rg + 8];
    }

    // stage fp32 per n-half, coalesced store
    float* stg = (float*)smem;               // [128][68] fp32
    for (int h = 0; h < 2; h++) {
        __syncthreads();
        if ((wn >> 1) == h) {
            const int cbase = (wn & 1) * 32 + q * 2;
            #pragma unroll
            for (int mi = 0; mi < 4; mi++) {
                const int r0 = wm * 64 + mi * 16 + g;
                #pragma unroll
                for (int ni = 0; ni < 4; ni++) {
                    const int c = cbase + ni * 8;
                    stg[r0 * 68 + c]           = acc[mi][ni][0] * inv0[mi];
                    stg[r0 * 68 + c + 1]       = acc[mi][ni][1] * inv0[mi];
                    stg[(r0 + 8) * 68 + c]     = acc[mi][ni][2] * inv1[mi];
                    stg[(r0 + 8) * 68 + c + 1] = acc[mi][ni][3] * inv1[mi];
                }
            }
        }
        __syncthreads();
        const int srow = tid >> 1;
        const int c0 = (tid & 1) * 32;
        float4* gp = (float4*)(out + (size_t)(b * TT + ti * 128 + srow) * CCD
                               + (size_t)cb * 128 + h * 64 + c0);
        const float4* sp = (const float4*)(stg + srow * 68 + c0);
        #pragma unroll
        for (int i = 0; i < 8; i++) gp[i] = sp[i];
    }
}

// =====================================================================
extern "C" void kernel_launch(void* const* d_in, const int* in_sizes, int n_in,
                              void* d_out, int out_size) {
    const float* x     = (const float*)d_in[0];
    const void*  idx   = d_in[1];
    const float* Wqq   = (const float*)d_in[2];
    const float* Wk    = (const float*)d_in[3];
    const float* Wkup  = (const float*)d_in[4];
    const float* Wv    = (const float*)d_in[5];
    const float* Wvup  = (const float*)d_in[6];
    const float* ktab  = (const float*)d_in[7];
    const float* vtab  = (const float*)d_in[8];
    const float* xq    = (const float*)d_in[9];
    const float* xk    = (const float*)d_in[10];
    const float* xv    = (const float*)d_in[11];
    const float* gq    = (const float*)d_in[12];
    const float* bq    = (const float*)d_in[13];
    const float* gk    = (const float*)d_in[14];
    const float* bk    = (const float*)d_in[15];
    const float* gv    = (const float*)d_in[16];
    const float* bv    = (const float*)d_in[17];
    float* out = (float*)d_out;

    idx_cvt_kernel<<<NROWS / 256, 256>>>(idx);
    proj_kernel<<<dim3(128, 5), 256>>>(x, Wqq, Wk, Wv);
    kup_kernel<<<NROWS / 32, 256>>>(Wkup, ktab);
    vup_kernel<<<NROWS / 16, 256>>>(Wvup, vtab);
    shift_ln_kernel<<<NROWS, 256>>>(0, xq, gq, bq);
    shift_ln_kernel<<<NROWS, 256>>>(1, xk, gk, bk);
    shift_ln_kernel<<<NROWS, 256>>>(2, xv, gv, bv);
    vt_cvt_kernel<<<dim3(CCD / 32, NROWS / 32), 256>>>();
    score_mma_kernel<<<dim3(16, 16, 4), 256, DYN_SMEM>>>();
    psum_reduce_kernel<<<NROWS / 256, 256>>>();
    pv_mma_kernel<<<dim3(8, 16, 4), 256, DYN_SMEM>>>(out);
}

// round 9
// speedup vs baseline: 1.5281x; 1.0909x over previous
#include <cuda_runtime.h>
#include <cuda_bf16.h>
#include <math.h>
#include <stdint.h>

#define TT 2048
#define BB 4
#define CCD 1024
#define QD 256
#define KVD 32
#define NPROJ 320
#define NROWS (BB*TT)       // 8192
#define VOCAB 50257

// ---------------- scratch (static device globals; no allocations) ----------------
__device__ __align__(16) float d_proj[NROWS * NPROJ];
__device__ __align__(16) float d_kraw[NROWS * QD];
__device__ __align__(16) float d_vraw[NROWS * CCD];
__device__ __align__(16) float d_vf[NROWS * CCD];
__device__ __align__(16) __nv_bfloat16 d_xh[NROWS * CCD];
__device__ __align__(16) __nv_bfloat16 d_xl[NROWS * CCD];
__device__ __align__(16) __nv_bfloat16 d_wh[NPROJ * CCD];
__device__ __align__(16) __nv_bfloat16 d_wl[NPROJ * CCD];
__device__ __align__(16) __nv_bfloat16 d_qh[NROWS * QD];
__device__ __align__(16) __nv_bfloat16 d_ql[NROWS * QD];
__device__ __align__(16) __nv_bfloat16 d_kh[NROWS * QD];
__device__ __align__(16) __nv_bfloat16 d_kl[NROWS * QD];
__device__ __align__(16) __nv_bfloat16 d_vth[(size_t)NROWS * CCD];  // [b][c][t]
__device__ __align__(16) __nv_bfloat16 d_vtl[(size_t)NROWS * CCD];
__device__ __align__(16) __nv_bfloat16 d_ph[(size_t)BB * TT * TT];  // P hi, [b][t][s]
__device__ __align__(16) __nv_bfloat16 d_pl[(size_t)BB * TT * TT];  // P lo
__device__ float d_psum[(size_t)NROWS * 64];    // per-row, per-32-col-stripe partials
__device__ float d_rowsum[NROWS];
__device__ int   d_idx32[NROWS];

// ---------------- warp-mma helpers (sm_80-class, legal on base sm_103) ----------------
__device__ __forceinline__ uint32_t smem_to_u32(const void* p) {
    uint32_t a;
    asm("{ .reg .u64 t; cvta.to.shared.u64 t, %1; cvt.u32.u64 %0, t; }" : "=r"(a) : "l"(p));
    return a;
}
__device__ __forceinline__ void ldsm4(uint32_t r[4], uint32_t a) {
    asm volatile("ldmatrix.sync.aligned.m8n8.x4.shared.b16 {%0,%1,%2,%3}, [%4];"
                 : "=r"(r[0]), "=r"(r[1]), "=r"(r[2]), "=r"(r[3]) : "r"(a));
}
__device__ __forceinline__ void ldsm2(uint32_t r[2], uint32_t a) {
    asm volatile("ldmatrix.sync.aligned.m8n8.x2.shared.b16 {%0,%1}, [%2];"
                 : "=r"(r[0]), "=r"(r[1]) : "r"(a));
}
__device__ __forceinline__ void mma_bf16(float c[4], const uint32_t a[4], const uint32_t b[2]) {
    asm volatile("mma.sync.aligned.m16n8k16.row.col.f32.bf16.bf16.f32 "
                 "{%0,%1,%2,%3}, {%4,%5,%6,%7}, {%8,%9}, {%0,%1,%2,%3};"
                 : "+f"(c[0]), "+f"(c[1]), "+f"(c[2]), "+f"(c[3])
                 : "r"(a[0]), "r"(a[1]), "r"(a[2]), "r"(a[3]), "r"(b[0]), "r"(b[1]));
}
__device__ __forceinline__ uint32_t pack_bf16x2(float lo, float hi) {
    uint32_t r;
    asm("cvt.rn.bf16x2.f32 %0, %1, %2;" : "=r"(r) : "f"(hi), "f"(lo));
    return r;
}

// smem tile offsets (bytes). rows x 40 bf16 (80B stride)
#define SQH 0
#define SQL 10240
#define SKH 20480
#define SKL 30720
#define DYN_SMEM 40960
// proj tiles: A 128x32 hi/lo, B 64x32 hi/lo
#define PB_H 20480
#define PB_L 25600
#define PROJ_SMEM 30720

// =====================================================================
// K0: idx normalize (int32/int64 auto-detect)
// =====================================================================
__global__ void idx_cvt_kernel(const void* __restrict__ raw) {
    const long long* p64 = (const long long*)raw;
    const int*       p32 = (const int*)raw;
    bool is64 = true;
    #pragma unroll
    for (int i = 0; i < 16; i++) {
        long long v = p64[i];
        if (v < 0 || v >= (long long)VOCAB) is64 = false;
    }
    int i = blockIdx.x * blockDim.x + threadIdx.x;
    if (i < NROWS) {
        int v = is64 ? (int)p64[i] : p32[i];
        if (v < 0) v = 0;
        if (v >= VOCAB) v = VOCAB - 1;
        d_idx32[i] = v;
    }
}

// =====================================================================
// K0b: fp32 -> bf16 hi/lo split. Destination selected INSIDE device code
// (passing __device__ symbols as host-side kernel args hands the kernel
//  the host shadow address — on GB300/ATS that silently writes host
//  memory instead of the device arrays; R7's rel_err=1.0 root cause).
//   which: 0 -> d_xh/d_xl, 1 -> d_wh/d_wl + 0 (Wqq),
//          2 -> +256*CCD (Wk), 3 -> +288*CCD (Wv)
// =====================================================================
__global__ void split_kernel(int which, const float* __restrict__ src, int n4) {
    int i = blockIdx.x * 256 + threadIdx.x;
    if (i >= n4) return;
    __nv_bfloat16 *dh, *dl;
    if (which == 0)      { dh = d_xh;             dl = d_xl; }
    else if (which == 1) { dh = d_wh;             dl = d_wl; }
    else if (which == 2) { dh = d_wh + 256 * CCD; dl = d_wl + 256 * CCD; }
    else                 { dh = d_wh + 288 * CCD; dl = d_wl + 288 * CCD; }
    float4 v = ((const float4*)src)[i];
    float hx = __bfloat162float(__float2bfloat16(v.x));
    float hy = __bfloat162float(__float2bfloat16(v.y));
    float hz = __bfloat162float(__float2bfloat16(v.z));
    float hw = __bfloat162float(__float2bfloat16(v.w));
    uint2 ph = make_uint2(pack_bf16x2(hx, hy), pack_bf16x2(hz, hw));
    uint2 pl = make_uint2(pack_bf16x2(v.x - hx, v.y - hy), pack_bf16x2(v.z - hz, v.w - hw));
    ((uint2*)dh)[i] = ph;
    ((uint2*)dl)[i] = pl;
}

// =====================================================================
// K1: projection GEMM via mma.sync. proj[m, n] = sum_c x[m,c] * W[n,c]
//   CTA 128(m) x 64(n), 8 warps (2m x 4n), warp 64x16, k-chunk 32.
//   3-term bf16 hi/lo. Output fp32 into d_proj (layout unchanged).
// =====================================================================
__global__ void __launch_bounds__(256) proj_mma_kernel() {
    extern __shared__ char smem[];
    const int nb = blockIdx.x * 64;
    const int mb = blockIdx.y * 128;
    const uint32_t sb = smem_to_u32(smem);
    const int tid  = threadIdx.x;
    const int lane = tid & 31;
    const int wid  = tid >> 5;
    const int wm = wid & 1;
    const int wn = wid >> 1;
    const int g = lane >> 2, q = lane & 3;

    float acc[4][2][4] = {};

    const int lrow = tid >> 1;
    const int lh   = tid & 1;
    const size_t arow = (size_t)(mb + lrow) * CCD;
    const uint32_t sdstA = lrow * 80 + lh * 32;
    const int blrow = tid >> 2;
    const int bq4   = tid & 3;
    const size_t brow = (size_t)(nb + blrow) * CCD;
    const uint32_t sdstB = blrow * 80 + bq4 * 16;

    for (int k0 = 0; k0 < CCD; k0 += 32) {
        {
            const uint4* axh = (const uint4*)(d_xh + arow + k0 + lh * 16);
            const uint4* axl = (const uint4*)(d_xl + arow + k0 + lh * 16);
            *(uint4*)(smem + SQH + sdstA)      = axh[0];
            *(uint4*)(smem + SQH + sdstA + 16) = axh[1];
            *(uint4*)(smem + SQL + sdstA)      = axl[0];
            *(uint4*)(smem + SQL + sdstA + 16) = axl[1];
            *(uint4*)(smem + PB_H + sdstB) = *(const uint4*)(d_wh + brow + k0 + bq4 * 8);
            *(uint4*)(smem + PB_L + sdstB) = *(const uint4*)(d_wl + brow + k0 + bq4 * 8);
        }
        __syncthreads();
        #pragma unroll
        for (int k16 = 0; k16 < 2; k16++) {
            const int kc = k16 * 16;
            uint32_t bh[2][2], bl[2][2];
            const int brw = lane & 7;
            const int bcl = kc + ((lane >> 3) & 1) * 8;
            #pragma unroll
            for (int ni = 0; ni < 2; ni++) {
                uint32_t boff = (wn * 16 + ni * 8 + brw) * 80 + bcl * 2;
                ldsm2(bh[ni], sb + PB_H + boff);
                ldsm2(bl[ni], sb + PB_L + boff);
            }
            const int arw = wm * 64 + (lane & 15);
            const int acl = kc + (lane >> 4) * 8;
            #pragma unroll
            for (int mi = 0; mi < 4; mi++) {
                uint32_t ah[4], al[4];
                uint32_t aoff = (arw + mi * 16) * 80 + acl * 2;
                ldsm4(ah, sb + SQH + aoff);
                ldsm4(al, sb + SQL + aoff);
                #pragma unroll
                for (int ni = 0; ni < 2; ni++) {
                    mma_bf16(acc[mi][ni], ah, bh[ni]);
                    mma_bf16(acc[mi][ni], ah, bl[ni]);
                    mma_bf16(acc[mi][ni], al, bh[ni]);
                }
            }
        }
        __syncthreads();
    }
    #pragma unroll
    for (int mi = 0; mi < 4; mi++) {
        const int r0 = mb + wm * 64 + mi * 16 + g;
        #pragma unroll
        for (int ni = 0; ni < 2; ni++) {
            const int c = nb + wn * 16 + ni * 8 + q * 2;
            *(float2*)&d_proj[(size_t)r0 * NPROJ + c]       = make_float2(acc[mi][ni][0], acc[mi][ni][1]);
            *(float2*)&d_proj[(size_t)(r0 + 8) * NPROJ + c] = make_float2(acc[mi][ni][2], acc[mi][ni][3]);
        }
    }
}

// =====================================================================
// K2a/K2b: low-rank up-projections (unchanged)
// =====================================================================
__global__ void kup_kernel(const float* __restrict__ Wkup, const float* __restrict__ ktab) {
    __shared__ float Ws[32 * 257];
    __shared__ float kds[32][32];
    const int tid = threadIdx.x;
    const int r0 = blockIdx.x * 32;
    for (int i2 = tid; i2 < QD * KVD; i2 += 256) {
        int o = i2 >> 5, d = i2 & 31;
        Ws[d * 257 + o] = Wkup[i2];
    }
    for (int i2 = tid; i2 < 32 * KVD; i2 += 256) {
        int rr = i2 >> 5, d = i2 & 31;
        kds[rr][d] = d_proj[(size_t)(r0 + rr) * NPROJ + 256 + d];
    }
    __syncthreads();
    float a[32];
    #pragma unroll
    for (int rr = 0; rr < 32; rr++) a[rr] = 0.f;
    #pragma unroll
    for (int d = 0; d < 32; d++) {
        float w = Ws[d * 257 + tid];
        #pragma unroll
        for (int rr = 0; rr < 32; rr++) a[rr] += kds[rr][d] * w;
    }
    #pragma unroll
    for (int rr = 0; rr < 32; rr++) {
        int ii = d_idx32[r0 + rr];
        d_kraw[(size_t)(r0 + rr) * QD + tid] = a[rr] * ktab[(size_t)ii * QD + tid];
    }
}

__global__ void vup_kernel(const float* __restrict__ Wvup, const float* __restrict__ vtab) {
    __shared__ float Wtc[32 * 257];
    __shared__ float vds[16][32];
    const int tid = threadIdx.x;
    const int r0 = blockIdx.x * 16;
    for (int i2 = tid; i2 < 16 * KVD; i2 += 256) {
        int rr = i2 >> 5, d = i2 & 31;
        vds[rr][d] = d_proj[(size_t)(r0 + rr) * NPROJ + 288 + d];
    }
    for (int j = 0; j < 4; j++) {
        __syncthreads();
        for (int i2 = tid; i2 < 256 * KVD; i2 += 256) {
            int cl = i2 >> 5, d = i2 & 31;
            Wtc[d * 257 + cl] = Wvup[(size_t)(j * 256 + cl) * KVD + d];
        }
        __syncthreads();
        const int c = j * 256 + tid;
        float a[16];
        #pragma unroll
        for (int rr = 0; rr < 16; rr++) a[rr] = 0.f;
        #pragma unroll
        for (int d = 0; d < 32; d++) {
            float w = Wtc[d * 257 + tid];
            #pragma unroll
            for (int rr = 0; rr < 16; rr++) a[rr] += vds[rr][d] * w;
        }
        #pragma unroll
        for (int rr = 0; rr < 16; rr++) {
            int ii = d_idx32[r0 + rr];
            d_vraw[(size_t)(r0 + rr) * CCD + c] = tanhf(a[rr]) * vtab[(size_t)ii * CCD + c];
        }
    }
}

// =====================================================================
// K3: time-shift + LayerNorm; q/k emit bf16 hi/lo, v emits fp32
// =====================================================================
__global__ void shift_ln_kernel(int which, const float* __restrict__ coef,
                                const float* __restrict__ g, const float* __restrict__ bta) {
    const float* raw; int stride, D;
    float* outf = nullptr; __nv_bfloat16 *oh = nullptr, *ol = nullptr;
    if (which == 0)      { raw = d_proj; stride = NPROJ; D = QD;  oh = d_qh; ol = d_ql; }
    else if (which == 1) { raw = d_kraw; stride = QD;    D = QD;  oh = d_kh; ol = d_kl; }
    else                 { raw = d_vraw; stride = CCD;   D = CCD; outf = d_vf; }
    const int r = blockIdx.x;
    const int t = r & (TT - 1);
    const float* cur = raw + (size_t)r * stride;
    const float* prv = cur - stride;
    float y[4];
    float s = 0.f, s2 = 0.f;
    int cnt = 0;
    for (int d = threadIdx.x; d < D; d += 256) {
        float c = cur[d];
        float p = (t > 0) ? prv[d] : 0.f;
        float v = c + (p - c) * coef[d];
        y[cnt++] = v;
        s += v; s2 += v * v;
    }
    #pragma unroll
    for (int o = 16; o; o >>= 1) {
        s  += __shfl_xor_sync(0xffffffffu, s,  o);
        s2 += __shfl_xor_sync(0xffffffffu, s2, o);
    }
    __shared__ float ws[8], ws2[8];
    __shared__ float smean, srstd;
    if ((threadIdx.x & 31) == 0) { ws[threadIdx.x >> 5] = s; ws2[threadIdx.x >> 5] = s2; }
    __syncthreads();
    if (threadIdx.x == 0) {
        float S = 0.f, S2 = 0.f;
        #pragma unroll
        for (int i = 0; i < 8; i++) { S += ws[i]; S2 += ws2[i]; }
        float mean = S / D;
        float var  = S2 / D - mean * mean;
        smean = mean;
        srstd = rsqrtf(var + 1e-5f);
    }
    __syncthreads();
    cnt = 0;
    for (int d = threadIdx.x; d < D; d += 256) {
        float o = (y[cnt++] - smean) * srstd * g[d] + bta[d];
        if (which == 2) {
            outf[(size_t)r * D + d] = o;
        } else {
            __nv_bfloat16 hi = __float2bfloat16(o);
            oh[(size_t)r * D + d] = hi;
            ol[(size_t)r * D + d] = __float2bfloat16(o - __bfloat162float(hi));
        }
    }
}

// =====================================================================
// K3b: transpose V -> Vt[b][c][t], split bf16 hi/lo
// =====================================================================
__global__ void vt_cvt_kernel() {
    __shared__ float ts[32][33];
    const int c0 = blockIdx.x * 32;
    const int r0 = blockIdx.y * 32;
    const int lx = threadIdx.x & 31;
    const int ly = threadIdx.x >> 5;
    #pragma unroll
    for (int i = 0; i < 4; i++) {
        int rr = ly + i * 8;
        ts[rr][lx] = d_vf[(size_t)(r0 + rr) * CCD + c0 + lx];
    }
    __syncthreads();
    const int bz = r0 >> 11;
    const int t0 = r0 & (TT - 1);
    #pragma unroll
    for (int i = 0; i < 4; i++) {
        int cc = ly + i * 8;
        float v = ts[lx][cc];
        size_t o = (size_t)(bz * CCD + c0 + cc) * TT + t0 + lx;
        __nv_bfloat16 hi = __float2bfloat16(v);
        d_vth[o] = hi;
        d_vtl[o] = __float2bfloat16(v - __bfloat162float(hi));
    }
}

// =====================================================================
// K4a: score via mma.sync (unchanged from R6 passing version)
// =====================================================================
__global__ void __launch_bounds__(256) score_mma_kernel() {
    extern __shared__ char smem[];
    const int tj = blockIdx.x, ti = blockIdx.y, b = blockIdx.z;
    if (tj > ti) return;
    const uint32_t sb = smem_to_u32(smem);
    const int tid  = threadIdx.x;
    const int lane = tid & 31;
    const int wid  = tid >> 5;
    const int wm = wid & 1;
    const int wn = wid >> 1;
    const int g = lane >> 2, q = lane & 3;

    float acc[4][4][4] = {};

    const int lrow = tid >> 1;
    const int lh   = tid & 1;
    const size_t qrow = (size_t)(b * TT + ti * 128 + lrow) * QD;
    const size_t krow = (size_t)(b * TT + tj * 128 + lrow) * QD;
    const uint32_t sdst = lrow * 80 + lh * 32;

    for (int k0 = 0; k0 < QD; k0 += 32) {
        {
            const uint4* gq_h = (const uint4*)(d_qh + qrow + k0 + lh * 16);
            const uint4* gq_l = (const uint4*)(d_ql + qrow + k0 + lh * 16);
            const uint4* gk_h = (const uint4*)(d_kh + krow + k0 + lh * 16);
            const uint4* gk_l = (const uint4*)(d_kl + krow + k0 + lh * 16);
            *(uint4*)(smem + SQH + sdst)      = gq_h[0];
            *(uint4*)(smem + SQH + sdst + 16) = gq_h[1];
            *(uint4*)(smem + SQL + sdst)      = gq_l[0];
            *(uint4*)(smem + SQL + sdst + 16) = gq_l[1];
            *(uint4*)(smem + SKH + sdst)      = gk_h[0];
            *(uint4*)(smem + SKH + sdst + 16) = gk_h[1];
            *(uint4*)(smem + SKL + sdst)      = gk_l[0];
            *(uint4*)(smem + SKL + sdst + 16) = gk_l[1];
        }
        __syncthreads();
        #pragma unroll
        for (int k16 = 0; k16 < 2; k16++) {
            const int kc = k16 * 16;
            uint32_t bh[4][2], bl[4][2];
            const int brow = lane & 7;
            const int bcol = kc + ((lane >> 3) & 1) * 8;
            #pragma unroll
            for (int ni = 0; ni < 4; ni++) {
                uint32_t boff = (wn * 32 + ni * 8 + brow) * 80 + bcol * 2;
                ldsm2(bh[ni], sb + SKH + boff);
                ldsm2(bl[ni], sb + SKL + boff);
            }
            const int arow = wm * 64 + (lane & 15);
            const int acol = kc + (lane >> 4) * 8;
            #pragma unroll
            for (int mi = 0; mi < 4; mi++) {
                uint32_t ah[4], al[4];
                uint32_t aoff = (arow + mi * 16) * 80 + acol * 2;
                ldsm4(ah, sb + SQH + aoff);
                ldsm4(al, sb + SQL + aoff);
                #pragma unroll
                for (int ni = 0; ni < 4; ni++) {
                    mma_bf16(acc[mi][ni], ah, bh[ni]);
                    mma_bf16(acc[mi][ni], ah, bl[ni]);
                    mma_bf16(acc[mi][ni], al, bh[ni]);
                }
            }
        }
        __syncthreads();
    }

    #pragma unroll
    for (int mi = 0; mi < 4; mi++) {
        const int tg0 = ti * 128 + wm * 64 + mi * 16 + g;
        const int tg1 = tg0 + 8;
        float ps0 = 0.f, ps1 = 0.f;
        #pragma unroll
        for (int ni = 0; ni < 4; ni++) {
            const int sg = tj * 128 + wn * 32 + ni * 8 + q * 2;
            #pragma unroll
            for (int e = 0; e < 4; e++) {
                const int col = sg + (e & 1);
                const int row = (e < 2) ? tg0 : tg1;
                float p = 0.f;
                if (col <= row) {
                    float d = acc[mi][ni][e];
                    float u = __expf(d * (1.f / 512.f));
                    float th = __fdividef(u - 1.f, u + 1.f);
                    p = __expf(64.f * th);
                }
                acc[mi][ni][e] = p;
                if (e < 2) ps0 += p; else ps1 += p;
            }
        }
        ps0 += __shfl_xor_sync(0xffffffffu, ps0, 1);
        ps0 += __shfl_xor_sync(0xffffffffu, ps0, 2);
        ps1 += __shfl_xor_sync(0xffffffffu, ps1, 1);
        ps1 += __shfl_xor_sync(0xffffffffu, ps1, 2);
        if (q == 0) {
            d_psum[(size_t)(b * TT + tg0) * 64 + tj * 4 + wn] = ps0;
            d_psum[(size_t)(b * TT + tg1) * 64 + tj * 4 + wn] = ps1;
        }
    }

    uint32_t* stg = (uint32_t*)smem;
    const int cpair = wn * 16 + q;
    for (int pass = 0; pass < 2; pass++) {
        __syncthreads();
        #pragma unroll
        for (int mi = 0; mi < 4; mi++) {
            const int r0 = wm * 64 + mi * 16 + g;
            #pragma unroll
            for (int ni = 0; ni < 4; ni++) {
                float v0 = acc[mi][ni][0], v1 = acc[mi][ni][1];
                float v2 = acc[mi][ni][2], v3 = acc[mi][ni][3];
                if (pass == 1) {
                    v0 -= __bfloat162float(__float2bfloat16(v0));
                    v1 -= __bfloat162float(__float2bfloat16(v1));
                    v2 -= __bfloat162float(__float2bfloat16(v2));
                    v3 -= __bfloat162float(__float2bfloat16(v3));
                }
                stg[r0 * 68 + cpair + ni * 4]       = pack_bf16x2(v0, v1);
                stg[(r0 + 8) * 68 + cpair + ni * 4] = pack_bf16x2(v2, v3);
            }
        }
        __syncthreads();
        __nv_bfloat16* gbase = (pass == 0) ? d_ph : d_pl;
        const int srow = tid >> 1;
        const int c0 = (tid & 1) * 32;
        uint4* gp = (uint4*)(gbase + (size_t)(b * TT + ti * 128 + srow) * TT
                             + (size_t)tj * 128 + (tid & 1) * 64);
        const uint4* sp = (const uint4*)(stg + srow * 68 + c0);
        #pragma unroll
        for (int i = 0; i < 8; i++) gp[i] = sp[i];
    }
}

// =====================================================================
// K4c: rowsum from 32-col stripe partials
// =====================================================================
__global__ void psum_reduce_kernel() {
    int r = blockIdx.x * 256 + threadIdx.x;
    int t = r & (TT - 1);
    int n = (t >> 5) + 1;
    const float* p = d_psum + (size_t)r * 64;
    float s = 0.f;
    for (int j = 0; j < n; j++) s += p[j];
    d_rowsum[r] = s;
}

// =====================================================================
// K4b: PV via mma.sync (unchanged from R6 passing version)
// =====================================================================
__global__ void __launch_bounds__(256) pv_mma_kernel(float* __restrict__ out) {
    extern __shared__ char smem[];
    const int cb = blockIdx.x, ti = blockIdx.y, b = blockIdx.z;
    const uint32_t sb = smem_to_u32(smem);
    const int tid  = threadIdx.x;
    const int lane = tid & 31;
    const int wid  = tid >> 5;
    const int wm = wid & 1;
    const int wn = wid >> 1;
    const int g = lane >> 2, q = lane & 3;

    float acc[4][4][4] = {};

    const int lrow = tid >> 1;
    const int lh   = tid & 1;
    const size_t prow = (size_t)(b * TT + ti * 128 + lrow) * TT;
    const size_t vrow = (size_t)(b * CCD + cb * 128 + lrow) * TT;
    const uint32_t sdst = lrow * 80 + lh * 32;

    const int kend = (ti + 1) * 128;
    for (int k0 = 0; k0 < kend; k0 += 32) {
        {
            const uint4* ga_h = (const uint4*)(d_ph + prow + k0 + lh * 16);
            const uint4* ga_l = (const uint4*)(d_pl + prow + k0 + lh * 16);
            const uint4* gb_h = (const uint4*)(d_vth + vrow + k0 + lh * 16);
            const uint4* gb_l = (const uint4*)(d_vtl + vrow + k0 + lh * 16);
            *(uint4*)(smem + SQH + sdst)      = ga_h[0];
            *(uint4*)(smem + SQH + sdst + 16) = ga_h[1];
            *(uint4*)(smem + SQL + sdst)      = ga_l[0];
            *(uint4*)(smem + SQL + sdst + 16) = ga_l[1];
            *(uint4*)(smem + SKH + sdst)      = gb_h[0];
            *(uint4*)(smem + SKH + sdst + 16) = gb_h[1];
            *(uint4*)(smem + SKL + sdst)      = gb_l[0];
            *(uint4*)(smem + SKL + sdst + 16) = gb_l[1];
        }
        __syncthreads();
        #pragma unroll
        for (int k16 = 0; k16 < 2; k16++) {
            const int kc = k16 * 16;
            uint32_t bh[4][2], bl[4][2];
            const int brow = lane & 7;
            const int bcol = kc + ((lane >> 3) & 1) * 8;
            #pragma unroll
            for (int ni = 0; ni < 4; ni++) {
                uint32_t boff = (wn * 32 + ni * 8 + brow) * 80 + bcol * 2;
                ldsm2(bh[ni], sb + SKH + boff);
                ldsm2(bl[ni], sb + SKL + boff);
            }
            const int arow = wm * 64 + (lane & 15);
            const int acol = kc + (lane >> 4) * 8;
            #pragma unroll
            for (int mi = 0; mi < 4; mi++) {
                uint32_t ah[4], al[4];
                uint32_t aoff = (arow + mi * 16) * 80 + acol * 2;
                ldsm4(ah, sb + SQH + aoff);
                ldsm4(al, sb + SQL + aoff);
                #pragma unroll
                for (int ni = 0; ni < 4; ni++) {
                    mma_bf16(acc[mi][ni], ah, bh[ni]);
                    mma_bf16(acc[mi][ni], ah, bl[ni]);
                    mma_bf16(acc[mi][ni], al, bh[ni]);
                }
            }
        }
        __syncthreads();
    }

    float inv0[4], inv1[4];
    #pragma unroll
    for (int mi = 0; mi < 4; mi++) {
        int rg = b * TT + ti * 128 + wm * 64 + mi * 16 + g;
        inv0[mi] = 1.f / d_rowsum[rg];
        inv1[mi] = 1.f / d_rowsum[rg + 8];
    }

    float* stg = (float*)smem;
    for (int h = 0; h < 2; h++) {
        __syncthreads();
        if ((wn >> 1) == h) {
            const int cbase = (wn & 1) * 32 + q * 2;
            #pragma unroll
            for (int mi = 0; mi < 4; mi++) {
                const int r0 = wm * 64 + mi * 16 + g;
                #pragma unroll
                for (int ni = 0; ni < 4; ni++) {
                    const int c = cbase + ni * 8;
                    stg[r0 * 68 + c]           = acc[mi][ni][0] * inv0[mi];
                    stg[r0 * 68 + c + 1]       = acc[mi][ni][1] * inv0[mi];
                    stg[(r0 + 8) * 68 + c]     = acc[mi][ni][2] * inv1[mi];
                    stg[(r0 + 8) * 68 + c + 1] = acc[mi][ni][3] * inv1[mi];
                }
            }
        }
        __syncthreads();
        const int srow = tid >> 1;
        const int c0 = (tid & 1) * 32;
        float4* gp = (float4*)(out + (size_t)(b * TT + ti * 128 + srow) * CCD
                               + (size_t)cb * 128 + h * 64 + c0);
        const float4* sp = (const float4*)(stg + srow * 68 + c0);
        #pragma unroll
        for (int i = 0; i < 8; i++) gp[i] = sp[i];
    }
}

// =====================================================================
extern "C" void kernel_launch(void* const* d_in, const int* in_sizes, int n_in,
                              void* d_out, int out_size) {
    const float* x     = (const float*)d_in[0];
    const void*  idx   = d_in[1];
    const float* Wqq   = (const float*)d_in[2];
    const float* Wk    = (const float*)d_in[3];
    const float* Wkup  = (const float*)d_in[4];
    const float* Wv    = (const float*)d_in[5];
    const float* Wvup  = (const float*)d_in[6];
    const float* ktab  = (const float*)d_in[7];
    const float* vtab  = (const float*)d_in[8];
    const float* xq    = (const float*)d_in[9];
    const float* xk    = (const float*)d_in[10];
    const float* xv    = (const float*)d_in[11];
    const float* gq    = (const float*)d_in[12];
    const float* bq    = (const float*)d_in[13];
    const float* gk    = (const float*)d_in[14];
    const float* bk    = (const float*)d_in[15];
    const float* gv    = (const float*)d_in[16];
    const float* bv    = (const float*)d_in[17];
    float* out = (float*)d_out;

    idx_cvt_kernel<<<NROWS / 256, 256>>>(idx);
    // hi/lo splits (destinations resolved device-side; only d_in ptrs cross)
    split_kernel<<<NROWS * CCD / 4 / 256, 256>>>(0, x, NROWS * CCD / 4);
    split_kernel<<<256 * CCD / 4 / 256, 256>>>(1, Wqq, 256 * CCD / 4);
    split_kernel<<<32 * CCD / 4 / 256, 256>>>(2, Wk, 32 * CCD / 4);
    split_kernel<<<32 * CCD / 4 / 256, 256>>>(3, Wv, 32 * CCD / 4);
    proj_mma_kernel<<<dim3(5, 64), 256, PROJ_SMEM>>>();
    kup_kernel<<<NROWS / 32, 256>>>(Wkup, ktab);
    vup_kernel<<<NROWS / 16, 256>>>(Wvup, vtab);
    shift_ln_kernel<<<NROWS, 256>>>(0, xq, gq, bq);
    shift_ln_kernel<<<NROWS, 256>>>(1, xk, gk, bk);
    shift_ln_kernel<<<NROWS, 256>>>(2, xv, gv, bv);
    vt_cvt_kernel<<<dim3(CCD / 32, NROWS / 32), 256>>>();
    score_mma_kernel<<<dim3(16, 16, 4), 256, DYN_SMEM>>>();
    psum_reduce_kernel<<<NROWS / 256, 256>>>();
    pv_mma_kernel<<<dim3(8, 16, 4), 256, DYN_SMEM>>>(out);
}

// round 10
// speedup vs baseline: 1.7174x; 1.1239x over previous
#include <cuda_runtime.h>
#include <cuda_bf16.h>
#include <math.h>
#include <stdint.h>

#define TT 2048
#define BB 4
#define CCD 1024
#define QD 256
#define KVD 32
#define NPROJ 320
#define NROWS (BB*TT)       // 8192
#define VOCAB 50257

// ---------------- scratch (static device globals; no allocations) ----------------
__device__ __align__(16) float d_proj[NROWS * NPROJ];
__device__ __align__(16) float d_kraw[NROWS * QD];
__device__ __align__(16) float d_vraw[NROWS * CCD];
__device__ __align__(16) __nv_bfloat16 d_xh[NROWS * CCD];
__device__ __align__(16) __nv_bfloat16 d_xl[NROWS * CCD];
__device__ __align__(16) __nv_bfloat16 d_wh[NPROJ * CCD];
__device__ __align__(16) __nv_bfloat16 d_wl[NPROJ * CCD];
__device__ __align__(16) __nv_bfloat16 d_qh[NROWS * QD];
__device__ __align__(16) __nv_bfloat16 d_ql[NROWS * QD];
__device__ __align__(16) __nv_bfloat16 d_kh[NROWS * QD];
__device__ __align__(16) __nv_bfloat16 d_kl[NROWS * QD];
__device__ __align__(16) __nv_bfloat16 d_vth[(size_t)NROWS * CCD];  // [b][c][t]
__device__ __align__(16) __nv_bfloat16 d_vtl[(size_t)NROWS * CCD];
__device__ __align__(16) __nv_bfloat16 d_ph[(size_t)BB * TT * TT];  // P hi, [b][t][s]
__device__ __align__(16) __nv_bfloat16 d_pl[(size_t)BB * TT * TT];  // P lo
__device__ float d_psum[(size_t)NROWS * 64];
__device__ float d_rowsum[NROWS];
__device__ float d_vmean[NROWS];
__device__ float d_vrstd[NROWS];
__device__ int   d_idx32[NROWS];

// ---------------- warp-mma / async helpers ----------------
__device__ __forceinline__ uint32_t smem_to_u32(const void* p) {
    uint32_t a;
    asm("{ .reg .u64 t; cvta.to.shared.u64 t, %1; cvt.u32.u64 %0, t; }" : "=r"(a) : "l"(p));
    return a;
}
__device__ __forceinline__ void ldsm4(uint32_t r[4], uint32_t a) {
    asm volatile("ldmatrix.sync.aligned.m8n8.x4.shared.b16 {%0,%1,%2,%3}, [%4];"
                 : "=r"(r[0]), "=r"(r[1]), "=r"(r[2]), "=r"(r[3]) : "r"(a));
}
__device__ __forceinline__ void ldsm2(uint32_t r[2], uint32_t a) {
    asm volatile("ldmatrix.sync.aligned.m8n8.x2.shared.b16 {%0,%1}, [%2];"
                 : "=r"(r[0]), "=r"(r[1]) : "r"(a));
}
__device__ __forceinline__ void mma_bf16(float c[4], const uint32_t a[4], const uint32_t b[2]) {
    asm volatile("mma.sync.aligned.m16n8k16.row.col.f32.bf16.bf16.f32 "
                 "{%0,%1,%2,%3}, {%4,%5,%6,%7}, {%8,%9}, {%0,%1,%2,%3};"
                 : "+f"(c[0]), "+f"(c[1]), "+f"(c[2]), "+f"(c[3])
                 : "r"(a[0]), "r"(a[1]), "r"(a[2]), "r"(a[3]), "r"(b[0]), "r"(b[1]));
}
__device__ __forceinline__ uint32_t pack_bf16x2(float lo, float hi) {
    uint32_t r;
    asm("cvt.rn.bf16x2.f32 %0, %1, %2;" : "=r"(r) : "f"(hi), "f"(lo));
    return r;
}
__device__ __forceinline__ void cp_async16(uint32_t sdst, const void* gsrc) {
    asm volatile("cp.async.ca.shared.global [%0], [%1], 16;" :: "r"(sdst), "l"(gsrc) : "memory");
}
#define CP_COMMIT() asm volatile("cp.async.commit_group;" ::: "memory")
#define CP_WAIT1()  asm volatile("cp.async.wait_group 1;" ::: "memory")
#define CP_WAIT0()  asm volatile("cp.async.wait_group 0;" ::: "memory")

// score smem offsets (80B stride tiles, as in passing R6/R9)
#define SQH 0
#define SQL 10240
#define SKH 20480
#define SKL 30720
#define SCORE_SMEM 40960
// proj tiles
#define PB_H 20480
#define PB_L 25600
#define PROJ_SMEM 30720
// pv pipelined: 2 stages x 4 arrays x (128 rows x 48B) = 49152 = 48KB exactly
#define PV_ARR   6144
#define PV_STAGE 24576
#define PV_SMEM  49152

// =====================================================================
// K0: idx normalize (int32/int64 auto-detect)
// =====================================================================
__global__ void idx_cvt_kernel(const void* __restrict__ raw) {
    const long long* p64 = (const long long*)raw;
    const int*       p32 = (const int*)raw;
    bool is64 = true;
    #pragma unroll
    for (int i = 0; i < 16; i++) {
        long long v = p64[i];
        if (v < 0 || v >= (long long)VOCAB) is64 = false;
    }
    int i = blockIdx.x * blockDim.x + threadIdx.x;
    if (i < NROWS) {
        int v = is64 ? (int)p64[i] : p32[i];
        if (v < 0) v = 0;
        if (v >= VOCAB) v = VOCAB - 1;
        d_idx32[i] = v;
    }
}

// =====================================================================
// K0b: X split (dest resolved device-side — never pass __device__ symbols
// as host-side kernel args; ATS makes that silently write host memory)
// =====================================================================
__global__ void xsplit_kernel(const float* __restrict__ src, int n4) {
    int i = blockIdx.x * 256 + threadIdx.x;
    if (i >= n4) return;
    float4 v = ((const float4*)src)[i];
    float hx = __bfloat162float(__float2bfloat16(v.x));
    float hy = __bfloat162float(__float2bfloat16(v.y));
    float hz = __bfloat162float(__float2bfloat16(v.z));
    float hw = __bfloat162float(__float2bfloat16(v.w));
    ((uint2*)d_xh)[i] = make_uint2(pack_bf16x2(hx, hy), pack_bf16x2(hz, hw));
    ((uint2*)d_xl)[i] = make_uint2(pack_bf16x2(v.x - hx, v.y - hy), pack_bf16x2(v.z - hz, v.w - hw));
}

// merged W split: rows [0,256)=Wqq, [256,288)=Wk, [288,320)=Wv
__global__ void wsplit_kernel(const float* __restrict__ Wqq, const float* __restrict__ Wk,
                              const float* __restrict__ Wv) {
    int i = blockIdx.x * 256 + threadIdx.x;           // float4 index, NPROJ*CCD/4 total
    if (i >= NPROJ * CCD / 4) return;
    int row = i >> 8;                                  // CCD/4 = 256 float4 per row
    int c4  = i & 255;
    const float* src;
    if (row < 256)      src = Wqq + (size_t)row * CCD;
    else if (row < 288) src = Wk  + (size_t)(row - 256) * CCD;
    else                src = Wv  + (size_t)(row - 288) * CCD;
    float4 v = ((const float4*)src)[c4];
    float hx = __bfloat162float(__float2bfloat16(v.x));
    float hy = __bfloat162float(__float2bfloat16(v.y));
    float hz = __bfloat162float(__float2bfloat16(v.z));
    float hw = __bfloat162float(__float2bfloat16(v.w));
    ((uint2*)d_wh)[i] = make_uint2(pack_bf16x2(hx, hy), pack_bf16x2(hz, hw));
    ((uint2*)d_wl)[i] = make_uint2(pack_bf16x2(v.x - hx, v.y - hy), pack_bf16x2(v.z - hz, v.w - hw));
}

// =====================================================================
// K1: projection GEMM via mma.sync (unchanged from passing R9)
// =====================================================================
__global__ void __launch_bounds__(256) proj_mma_kernel() {
    extern __shared__ char smem[];
    const int nb = blockIdx.x * 64;
    const int mb = blockIdx.y * 128;
    const uint32_t sb = smem_to_u32(smem);
    const int tid  = threadIdx.x;
    const int lane = tid & 31;
    const int wid  = tid >> 5;
    const int wm = wid & 1;
    const int wn = wid >> 1;
    const int g = lane >> 2, q = lane & 3;

    float acc[4][2][4] = {};

    const int lrow = tid >> 1;
    const int lh   = tid & 1;
    const size_t arow = (size_t)(mb + lrow) * CCD;
    const uint32_t sdstA = lrow * 80 + lh * 32;
    const int blrow = tid >> 2;
    const int bq4   = tid & 3;
    const size_t brow = (size_t)(nb + blrow) * CCD;
    const uint32_t sdstB = blrow * 80 + bq4 * 16;

    for (int k0 = 0; k0 < CCD; k0 += 32) {
        {
            const uint4* axh = (const uint4*)(d_xh + arow + k0 + lh * 16);
            const uint4* axl = (const uint4*)(d_xl + arow + k0 + lh * 16);
            *(uint4*)(smem + SQH + sdstA)      = axh[0];
            *(uint4*)(smem + SQH + sdstA + 16) = axh[1];
            *(uint4*)(smem + SQL + sdstA)      = axl[0];
            *(uint4*)(smem + SQL + sdstA + 16) = axl[1];
            *(uint4*)(smem + PB_H + sdstB) = *(const uint4*)(d_wh + brow + k0 + bq4 * 8);
            *(uint4*)(smem + PB_L + sdstB) = *(const uint4*)(d_wl + brow + k0 + bq4 * 8);
        }
        __syncthreads();
        #pragma unroll
        for (int k16 = 0; k16 < 2; k16++) {
            const int kc = k16 * 16;
            uint32_t bh[2][2], bl[2][2];
            const int brw = lane & 7;
            const int bcl = kc + ((lane >> 3) & 1) * 8;
            #pragma unroll
            for (int ni = 0; ni < 2; ni++) {
                uint32_t boff = (wn * 16 + ni * 8 + brw) * 80 + bcl * 2;
                ldsm2(bh[ni], sb + PB_H + boff);
                ldsm2(bl[ni], sb + PB_L + boff);
            }
            const int arw = wm * 64 + (lane & 15);
            const int acl = kc + (lane >> 4) * 8;
            #pragma unroll
            for (int mi = 0; mi < 4; mi++) {
                uint32_t ah[4], al[4];
                uint32_t aoff = (arw + mi * 16) * 80 + acl * 2;
                ldsm4(ah, sb + SQH + aoff);
                ldsm4(al, sb + SQL + aoff);
                #pragma unroll
                for (int ni = 0; ni < 2; ni++) {
                    mma_bf16(acc[mi][ni], ah, bh[ni]);
                    mma_bf16(acc[mi][ni], ah, bl[ni]);
                    mma_bf16(acc[mi][ni], al, bh[ni]);
                }
            }
        }
        __syncthreads();
    }
    #pragma unroll
    for (int mi = 0; mi < 4; mi++) {
        const int r0 = mb + wm * 64 + mi * 16 + g;
        #pragma unroll
        for (int ni = 0; ni < 2; ni++) {
            const int c = nb + wn * 16 + ni * 8 + q * 2;
            *(float2*)&d_proj[(size_t)r0 * NPROJ + c]       = make_float2(acc[mi][ni][0], acc[mi][ni][1]);
            *(float2*)&d_proj[(size_t)(r0 + 8) * NPROJ + c] = make_float2(acc[mi][ni][2], acc[mi][ni][3]);
        }
    }
}

// =====================================================================
// K2a/K2b: low-rank up-projections (unchanged)
// =====================================================================
__global__ void kup_kernel(const float* __restrict__ Wkup, const float* __restrict__ ktab) {
    __shared__ float Ws[32 * 257];
    __shared__ float kds[32][32];
    const int tid = threadIdx.x;
    const int r0 = blockIdx.x * 32;
    for (int i2 = tid; i2 < QD * KVD; i2 += 256) {
        int o = i2 >> 5, d = i2 & 31;
        Ws[d * 257 + o] = Wkup[i2];
    }
    for (int i2 = tid; i2 < 32 * KVD; i2 += 256) {
        int rr = i2 >> 5, d = i2 & 31;
        kds[rr][d] = d_proj[(size_t)(r0 + rr) * NPROJ + 256 + d];
    }
    __syncthreads();
    float a[32];
    #pragma unroll
    for (int rr = 0; rr < 32; rr++) a[rr] = 0.f;
    #pragma unroll
    for (int d = 0; d < 32; d++) {
        float w = Ws[d * 257 + tid];
        #pragma unroll
        for (int rr = 0; rr < 32; rr++) a[rr] += kds[rr][d] * w;
    }
    #pragma unroll
    for (int rr = 0; rr < 32; rr++) {
        int ii = d_idx32[r0 + rr];
        d_kraw[(size_t)(r0 + rr) * QD + tid] = a[rr] * ktab[(size_t)ii * QD + tid];
    }
}

__global__ void vup_kernel(const float* __restrict__ Wvup, const float* __restrict__ vtab) {
    __shared__ float Wtc[32 * 257];
    __shared__ float vds[16][32];
    const int tid = threadIdx.x;
    const int r0 = blockIdx.x * 16;
    for (int i2 = tid; i2 < 16 * KVD; i2 += 256) {
        int rr = i2 >> 5, d = i2 & 31;
        vds[rr][d] = d_proj[(size_t)(r0 + rr) * NPROJ + 288 + d];
    }
    for (int j = 0; j < 4; j++) {
        __syncthreads();
        for (int i2 = tid; i2 < 256 * KVD; i2 += 256) {
            int cl = i2 >> 5, d = i2 & 31;
            Wtc[d * 257 + cl] = Wvup[(size_t)(j * 256 + cl) * KVD + d];
        }
        __syncthreads();
        const int c = j * 256 + tid;
        float a[16];
        #pragma unroll
        for (int rr = 0; rr < 16; rr++) a[rr] = 0.f;
        #pragma unroll
        for (int d = 0; d < 32; d++) {
            float w = Wtc[d * 257 + tid];
            #pragma unroll
            for (int rr = 0; rr < 16; rr++) a[rr] += vds[rr][d] * w;
        }
        #pragma unroll
        for (int rr = 0; rr < 16; rr++) {
            int ii = d_idx32[r0 + rr];
            d_vraw[(size_t)(r0 + rr) * CCD + c] = tanhf(a[rr]) * vtab[(size_t)ii * CCD + c];
        }
    }
}

// =====================================================================
// K3: q/k time-shift + LayerNorm, warp-per-row (D=256, 8 rows/block)
// =====================================================================
__global__ void qk_ln_kernel(int which, const float* __restrict__ coef,
                             const float* __restrict__ g, const float* __restrict__ bta) {
    const float* raw; int stride;
    __nv_bfloat16 *oh, *ol;
    if (which == 0) { raw = d_proj; stride = NPROJ; oh = d_qh; ol = d_ql; }
    else            { raw = d_kraw; stride = QD;    oh = d_kh; ol = d_kl; }
    const int r = blockIdx.x * 8 + (threadIdx.x >> 5);
    const int lane = threadIdx.x & 31;
    const int t = r & (TT - 1);
    const float* cur = raw + (size_t)r * stride;
    const float* prv = cur - stride;
    float y[8];
    float s = 0.f, s2 = 0.f;
    #pragma unroll
    for (int j = 0; j < 8; j++) {
        int d = j * 32 + lane;
        float c = cur[d];
        float p = (t > 0) ? prv[d] : 0.f;
        float v = c + (p - c) * coef[d];
        y[j] = v; s += v; s2 += v * v;
    }
    #pragma unroll
    for (int o = 16; o; o >>= 1) {
        s  += __shfl_xor_sync(0xffffffffu, s,  o);
        s2 += __shfl_xor_sync(0xffffffffu, s2, o);
    }
    float mean = s * (1.f / QD);
    float var  = s2 * (1.f / QD) - mean * mean;
    float rstd = rsqrtf(var + 1e-5f);
    #pragma unroll
    for (int j = 0; j < 8; j++) {
        int d = j * 32 + lane;
        float o = (y[j] - mean) * rstd * g[d] + bta[d];
        __nv_bfloat16 hi = __float2bfloat16(o);
        oh[(size_t)r * QD + d] = hi;
        ol[(size_t)r * QD + d] = __float2bfloat16(o - __bfloat162float(hi));
    }
}

// =====================================================================
// K3v: v shift+LN statistics only (warp-per-row, D=1024)
// =====================================================================
__global__ void v_stats_kernel(const float* __restrict__ coef) {
    const int r = blockIdx.x * 8 + (threadIdx.x >> 5);
    const int lane = threadIdx.x & 31;
    const int t = r & (TT - 1);
    const float4* cur = (const float4*)(d_vraw + (size_t)r * CCD);
    const float4* prv = cur - CCD / 4;
    const float4* cf  = (const float4*)coef;
    float s = 0.f, s2 = 0.f;
    #pragma unroll
    for (int j = 0; j < 8; j++) {
        int d4 = j * 32 + lane;
        float4 c = cur[d4];
        float4 p = (t > 0) ? prv[d4] : make_float4(0.f, 0.f, 0.f, 0.f);
        float4 w = cf[d4];
        float vx = c.x + (p.x - c.x) * w.x;
        float vy = c.y + (p.y - c.y) * w.y;
        float vz = c.z + (p.z - c.z) * w.z;
        float vw = c.w + (p.w - c.w) * w.w;
        s  += vx + vy + vz + vw;
        s2 += vx * vx + vy * vy + vz * vz + vw * vw;
    }
    #pragma unroll
    for (int o = 16; o; o >>= 1) {
        s  += __shfl_xor_sync(0xffffffffu, s,  o);
        s2 += __shfl_xor_sync(0xffffffffu, s2, o);
    }
    if (lane == 0) {
        float mean = s * (1.f / CCD);
        float var  = s2 * (1.f / CCD) - mean * mean;
        d_vmean[r] = mean;
        d_vrstd[r] = rsqrtf(var + 1e-5f);
    }
}

// =====================================================================
// K3b: fused shift+LN+transpose+split: vraw -> Vt[b][c][t] bf16 hi/lo
// =====================================================================
__global__ void vt_cvt_kernel(const float* __restrict__ xv, const float* __restrict__ gv,
                              const float* __restrict__ bv) {
    __shared__ float ts[33][33];
    const int c0 = blockIdx.x * 32;
    const int r0 = blockIdx.y * 32;
    // load rows r0-1 .. r0+31 (33 rows)
    for (int i2 = threadIdx.x; i2 < 33 * 32; i2 += 256) {
        int rr = i2 >> 5, cc = i2 & 31;
        int grow = r0 - 1 + rr;
        if (grow < 0) grow = 0;                 // value unused (masked by t==0)
        ts[rr][cc] = d_vraw[(size_t)grow * CCD + c0 + cc];
    }
    __syncthreads();
    const int lx = threadIdx.x & 31;            // row-in-tile (t)
    const int ly = threadIdx.x >> 5;            // 0..7
    const int bz = r0 >> 11;
    const int t0 = r0 & (TT - 1);
    const int t  = t0 + lx;
    const int r  = r0 + lx;
    const float mean = d_vmean[r];
    const float rstd = d_vrstd[r];
    #pragma unroll
    for (int i = 0; i < 4; i++) {
        int cc = ly + i * 8;
        int c  = c0 + cc;
        float curv = ts[lx + 1][cc];
        float prev = (t > 0) ? ts[lx][cc] : 0.f;
        float y = curv + (prev - curv) * xv[c];
        float v = (y - mean) * rstd * gv[c] + bv[c];
        size_t o = (size_t)(bz * CCD + c) * TT + t;
        __nv_bfloat16 hi = __float2bfloat16(v);
        d_vth[o] = hi;
        d_vtl[o] = __float2bfloat16(v - __bfloat162float(hi));
    }
}

// =====================================================================
// K4a: score via mma.sync (structure from passing R9; heavy-ti first)
// =====================================================================
__global__ void __launch_bounds__(256) score_mma_kernel() {
    extern __shared__ char smem[];
    const int tj = blockIdx.x, ti = 15 - blockIdx.y, b = blockIdx.z;
    if (tj > ti) return;
    const uint32_t sb = smem_to_u32(smem);
    const int tid  = threadIdx.x;
    const int lane = tid & 31;
    const int wid  = tid >> 5;
    const int wm = wid & 1;
    const int wn = wid >> 1;
    const int g = lane >> 2, q = lane & 3;

    float acc[4][4][4] = {};

    const int lrow = tid >> 1;
    const int lh   = tid & 1;
    const size_t qrow = (size_t)(b * TT + ti * 128 + lrow) * QD;
    const size_t krow = (size_t)(b * TT + tj * 128 + lrow) * QD;
    const uint32_t sdst = lrow * 80 + lh * 32;

    for (int k0 = 0; k0 < QD; k0 += 32) {
        {
            const uint4* gq_h = (const uint4*)(d_qh + qrow + k0 + lh * 16);
            const uint4* gq_l = (const uint4*)(d_ql + qrow + k0 + lh * 16);
            const uint4* gk_h = (const uint4*)(d_kh + krow + k0 + lh * 16);
            const uint4* gk_l = (const uint4*)(d_kl + krow + k0 + lh * 16);
            *(uint4*)(smem + SQH + sdst)      = gq_h[0];
            *(uint4*)(smem + SQH + sdst + 16) = gq_h[1];
            *(uint4*)(smem + SQL + sdst)      = gq_l[0];
            *(uint4*)(smem + SQL + sdst + 16) = gq_l[1];
            *(uint4*)(smem + SKH + sdst)      = gk_h[0];
            *(uint4*)(smem + SKH + sdst + 16) = gk_h[1];
            *(uint4*)(smem + SKL + sdst)      = gk_l[0];
            *(uint4*)(smem + SKL + sdst + 16) = gk_l[1];
        }
        __syncthreads();
        #pragma unroll
        for (int k16 = 0; k16 < 2; k16++) {
            const int kc = k16 * 16;
            uint32_t bh[4][2], bl[4][2];
            const int brow = lane & 7;
            const int bcol = kc + ((lane >> 3) & 1) * 8;
            #pragma unroll
            for (int ni = 0; ni < 4; ni++) {
                uint32_t boff = (wn * 32 + ni * 8 + brow) * 80 + bcol * 2;
                ldsm2(bh[ni], sb + SKH + boff);
                ldsm2(bl[ni], sb + SKL + boff);
            }
            const int arow = wm * 64 + (lane & 15);
            const int acol = kc + (lane >> 4) * 8;
            #pragma unroll
            for (int mi = 0; mi < 4; mi++) {
                uint32_t ah[4], al[4];
                uint32_t aoff = (arow + mi * 16) * 80 + acol * 2;
                ldsm4(ah, sb + SQH + aoff);
                ldsm4(al, sb + SQL + aoff);
                #pragma unroll
                for (int ni = 0; ni < 4; ni++) {
                    mma_bf16(acc[mi][ni], ah, bh[ni]);
                    mma_bf16(acc[mi][ni], ah, bl[ni]);
                    mma_bf16(acc[mi][ni], al, bh[ni]);
                }
            }
        }
        __syncthreads();
    }

    #pragma unroll
    for (int mi = 0; mi < 4; mi++) {
        const int tg0 = ti * 128 + wm * 64 + mi * 16 + g;
        const int tg1 = tg0 + 8;
        float ps0 = 0.f, ps1 = 0.f;
        #pragma unroll
        for (int ni = 0; ni < 4; ni++) {
            const int sg = tj * 128 + wn * 32 + ni * 8 + q * 2;
            #pragma unroll
            for (int e = 0; e < 4; e++) {
                const int col = sg + (e & 1);
                const int row = (e < 2) ? tg0 : tg1;
                float p = 0.f;
                if (col <= row) {
                    float d = acc[mi][ni][e];
                    float u = __expf(d * (1.f / 512.f));
                    float th = __fdividef(u - 1.f, u + 1.f);
                    p = __expf(64.f * th);
                }
                acc[mi][ni][e] = p;
                if (e < 2) ps0 += p; else ps1 += p;
            }
        }
        ps0 += __shfl_xor_sync(0xffffffffu, ps0, 1);
        ps0 += __shfl_xor_sync(0xffffffffu, ps0, 2);
        ps1 += __shfl_xor_sync(0xffffffffu, ps1, 1);
        ps1 += __shfl_xor_sync(0xffffffffu, ps1, 2);
        if (q == 0) {
            d_psum[(size_t)(b * TT + tg0) * 64 + tj * 4 + wn] = ps0;
            d_psum[(size_t)(b * TT + tg1) * 64 + tj * 4 + wn] = ps1;
        }
    }

    uint32_t* stg = (uint32_t*)smem;
    const int cpair = wn * 16 + q;
    for (int pass = 0; pass < 2; pass++) {
        __syncthreads();
        #pragma unroll
        for (int mi = 0; mi < 4; mi++) {
            const int r0 = wm * 64 + mi * 16 + g;
            #pragma unroll
            for (int ni = 0; ni < 4; ni++) {
                float v0 = acc[mi][ni][0], v1 = acc[mi][ni][1];
                float v2 = acc[mi][ni][2], v3 = acc[mi][ni][3];
                if (pass == 1) {
                    v0 -= __bfloat162float(__float2bfloat16(v0));
                    v1 -= __bfloat162float(__float2bfloat16(v1));
                    v2 -= __bfloat162float(__float2bfloat16(v2));
                    v3 -= __bfloat162float(__float2bfloat16(v3));
                }
                stg[r0 * 68 + cpair + ni * 4]       = pack_bf16x2(v0, v1);
                stg[(r0 + 8) * 68 + cpair + ni * 4] = pack_bf16x2(v2, v3);
            }
        }
        __syncthreads();
        __nv_bfloat16* gbase = (pass == 0) ? d_ph : d_pl;
        const int srow = tid >> 1;
        const int c0 = (tid & 1) * 32;
        uint4* gp = (uint4*)(gbase + (size_t)(b * TT + ti * 128 + srow) * TT
                             + (size_t)tj * 128 + (tid & 1) * 64);
        const uint4* sp = (const uint4*)(stg + srow * 68 + c0);
        #pragma unroll
        for (int i = 0; i < 8; i++) gp[i] = sp[i];
    }
}

// =====================================================================
// K4c: rowsum from 32-col stripe partials
// =====================================================================
__global__ void psum_reduce_kernel() {
    int r = blockIdx.x * 256 + threadIdx.x;
    int t = r & (TT - 1);
    int n = (t >> 5) + 1;
    const float* p = d_psum + (size_t)r * 64;
    float s = 0.f;
    for (int j = 0; j < n; j++) s += p[j];
    d_rowsum[r] = s;
}

// =====================================================================
// K4b: PV via mma.sync, cp.async 2-stage pipeline (k-chunk 16).
//   smem: 2 stages x {Ph, Pl, Vh, Vl} x 128 rows x 48B (32B payload).
//   48B stride => ldmatrix bank-conflict-free, 16B aligned.
// =====================================================================
__global__ void __launch_bounds__(256, 2) pv_mma_kernel(float* __restrict__ out) {
    extern __shared__ char smem[];
    const int cb = blockIdx.x, ti = 15 - blockIdx.y, b = blockIdx.z;
    const uint32_t sb = smem_to_u32(smem);
    const int tid  = threadIdx.x;
    const int lane = tid & 31;
    const int wid  = tid >> 5;
    const int wm = wid & 1;
    const int wn = wid >> 1;
    const int g = lane >> 2, q = lane & 3;

    float acc[4][4][4] = {};

    // loader: each thread owns (row = tid>>1, half = tid&1) for all 4 arrays
    const int lrow = tid >> 1;
    const int lh   = tid & 1;
    const size_t poff = (size_t)(b * TT + ti * 128 + lrow) * TT + lh * 8;
    const size_t voff = (size_t)(b * CCD + cb * 128 + lrow) * TT + lh * 8;
    const __nv_bfloat16* gsrc[4] = { d_ph + poff, d_pl + poff, d_vth + voff, d_vtl + voff };
    const uint32_t sldst = sb + lrow * 48 + lh * 16;

    const int nc = (ti + 1) * 8;      // k16 chunks

    // prologue: stage 0
    #pragma unroll
    for (int a = 0; a < 4; a++) cp_async16(sldst + a * PV_ARR, gsrc[a]);
    CP_COMMIT();

    for (int c = 0; c < nc; c++) {
        const uint32_t st = (c & 1) * PV_STAGE;
        if (c + 1 < nc) {
            const uint32_t st2 = ((c + 1) & 1) * PV_STAGE;
            const int k1 = (c + 1) * 16;
            #pragma unroll
            for (int a = 0; a < 4; a++) cp_async16(sldst + st2 + a * PV_ARR, gsrc[a] + k1);
            CP_COMMIT();
            CP_WAIT1();
        } else {
            CP_WAIT0();
        }
        __syncthreads();
        // compute one k16 on stage st
        {
            uint32_t bh[4][2], bl[4][2];
            const int brow = lane & 7;
            const uint32_t bsel = ((lane >> 3) & 1) * 16;
            #pragma unroll
            for (int ni = 0; ni < 4; ni++) {
                uint32_t boff = (wn * 32 + ni * 8 + brow) * 48 + bsel;
                ldsm2(bh[ni], sb + st + 2 * PV_ARR + boff);
                ldsm2(bl[ni], sb + st + 3 * PV_ARR + boff);
            }
            const int arow = wm * 64 + (lane & 15);
            const uint32_t asel = (lane >> 4) * 16;
            #pragma unroll
            for (int mi = 0; mi < 4; mi++) {
                uint32_t ah[4], al[4];
                uint32_t aoff = (arow + mi * 16) * 48 + asel;
                ldsm4(ah, sb + st + aoff);
                ldsm4(al, sb + st + 1 * PV_ARR + aoff);
                #pragma unroll
                for (int ni = 0; ni < 4; ni++) {
                    mma_bf16(acc[mi][ni], ah, bh[ni]);
                    mma_bf16(acc[mi][ni], ah, bl[ni]);
                    mma_bf16(acc[mi][ni], al, bh[ni]);
                }
            }
        }
        __syncthreads();
    }

    float inv0[4], inv1[4];
    #pragma unroll
    for (int mi = 0; mi < 4; mi++) {
        int rg = b * TT + ti * 128 + wm * 64 + mi * 16 + g;
        inv0[mi] = 1.f / d_rowsum[rg];
        inv1[mi] = 1.f / d_rowsum[rg + 8];
    }

    float* stg = (float*)smem;               // [128][68] fp32, 34816B < 49152B
    for (int h = 0; h < 2; h++) {
        __syncthreads();
        if ((wn >> 1) == h) {
            const int cbase = (wn & 1) * 32 + q * 2;
            #pragma unroll
            for (int mi = 0; mi < 4; mi++) {
                const int r0 = wm * 64 + mi * 16 + g;
                #pragma unroll
                for (int ni = 0; ni < 4; ni++) {
                    const int c = cbase + ni * 8;
                    stg[r0 * 68 + c]           = acc[mi][ni][0] * inv0[mi];
                    stg[r0 * 68 + c + 1]       = acc[mi][ni][1] * inv0[mi];
                    stg[(r0 + 8) * 68 + c]     = acc[mi][ni][2] * inv1[mi];
                    stg[(r0 + 8) * 68 + c + 1] = acc[mi][ni][3] * inv1[mi];
                }
            }
        }
        __syncthreads();
        const int srow = tid >> 1;
        const int c0 = (tid & 1) * 32;
        float4* gp = (float4*)(out + (size_t)(b * TT + ti * 128 + srow) * CCD
                               + (size_t)cb * 128 + h * 64 + c0);
        const float4* sp = (const float4*)(stg + srow * 68 + c0);
        #pragma unroll
        for (int i = 0; i < 8; i++) gp[i] = sp[i];
    }
}

// =====================================================================
extern "C" void kernel_launch(void* const* d_in, const int* in_sizes, int n_in,
                              void* d_out, int out_size) {
    const float* x     = (const float*)d_in[0];
    const void*  idx   = d_in[1];
    const float* Wqq   = (const float*)d_in[2];
    const float* Wk    = (const float*)d_in[3];
    const float* Wkup  = (const float*)d_in[4];
    const float* Wv    = (const float*)d_in[5];
    const float* Wvup  = (const float*)d_in[6];
    const float* ktab  = (const float*)d_in[7];
    const float* vtab  = (const float*)d_in[8];
    const float* xq    = (const float*)d_in[9];
    const float* xk    = (const float*)d_in[10];
    const float* xv    = (const float*)d_in[11];
    const float* gq    = (const float*)d_in[12];
    const float* bq    = (const float*)d_in[13];
    const float* gk    = (const float*)d_in[14];
    const float* bk    = (const float*)d_in[15];
    const float* gv    = (const float*)d_in[16];
    const float* bv    = (const float*)d_in[17];
    float* out = (float*)d_out;

    idx_cvt_kernel<<<NROWS / 256, 256>>>(idx);
    xsplit_kernel<<<NROWS * CCD / 4 / 256, 256>>>(x, NROWS * CCD / 4);
    wsplit_kernel<<<NPROJ * CCD / 4 / 256, 256>>>(Wqq, Wk, Wv);
    proj_mma_kernel<<<dim3(5, 64), 256, PROJ_SMEM>>>();
    kup_kernel<<<NROWS / 32, 256>>>(Wkup, ktab);
    vup_kernel<<<NROWS / 16, 256>>>(Wvup, vtab);
    qk_ln_kernel<<<NROWS / 8, 256>>>(0, xq, gq, bq);
    qk_ln_kernel<<<NROWS / 8, 256>>>(1, xk, gk, bk);
    v_stats_kernel<<<NROWS / 8, 256>>>(xv);
    vt_cvt_kernel<<<dim3(CCD / 32, NROWS / 32), 256>>>(xv, gv, bv);
    score_mma_kernel<<<dim3(16, 16, 4), 256, SCORE_SMEM>>>();
    psum_reduce_kernel<<<NROWS / 256, 256>>>();
    pv_mma_kernel<<<dim3(8, 16, 4), 256, PV_SMEM>>>(out);
}

// round 11
// speedup vs baseline: 1.7373x; 1.0116x over previous
#include <cuda_runtime.h>
#include <cuda_bf16.h>
#include <math.h>
#include <stdint.h>

#define TT 2048
#define BB 4
#define CCD 1024
#define QD 256
#define KVD 32
#define NPROJ 320
#define NROWS (BB*TT)       // 8192
#define VOCAB 50257

// ---------------- scratch (static device globals; no allocations) ----------------
__device__ __align__(16) float d_proj[NROWS * NPROJ];
__device__ __align__(16) float d_kraw[NROWS * QD];
__device__ __align__(16) float d_vraw[NROWS * CCD];
__device__ __align__(16) __nv_bfloat16 d_xh[NROWS * CCD];
__device__ __align__(16) __nv_bfloat16 d_xl[NROWS * CCD];
__device__ __align__(16) __nv_bfloat16 d_wh[NPROJ * CCD];
__device__ __align__(16) __nv_bfloat16 d_wl[NPROJ * CCD];
__device__ __align__(16) __nv_bfloat16 d_qh[NROWS * QD];
__device__ __align__(16) __nv_bfloat16 d_ql[NROWS * QD];
__device__ __align__(16) __nv_bfloat16 d_kh[NROWS * QD];
__device__ __align__(16) __nv_bfloat16 d_kl[NROWS * QD];
__device__ __align__(16) __nv_bfloat16 d_vth[(size_t)NROWS * CCD];  // [b][c][t]
__device__ __align__(16) __nv_bfloat16 d_vtl[(size_t)NROWS * CCD];
__device__ __align__(16) __nv_bfloat16 d_ph[(size_t)BB * TT * TT];  // P hi, [b][t][s]
__device__ __align__(16) __nv_bfloat16 d_pl[(size_t)BB * TT * TT];  // P lo
__device__ float d_psum[(size_t)NROWS * 64];
__device__ float d_rowsum[NROWS];
__device__ float d_vmean[NROWS];
__device__ float d_vrstd[NROWS];
__device__ int   d_idx32[NROWS];

// ---------------- warp-mma / async helpers ----------------
__device__ __forceinline__ uint32_t smem_to_u32(const void* p) {
    uint32_t a;
    asm("{ .reg .u64 t; cvta.to.shared.u64 t, %1; cvt.u32.u64 %0, t; }" : "=r"(a) : "l"(p));
    return a;
}
__device__ __forceinline__ void ldsm4(uint32_t r[4], uint32_t a) {
    asm volatile("ldmatrix.sync.aligned.m8n8.x4.shared.b16 {%0,%1,%2,%3}, [%4];"
                 : "=r"(r[0]), "=r"(r[1]), "=r"(r[2]), "=r"(r[3]) : "r"(a));
}
__device__ __forceinline__ void ldsm2(uint32_t r[2], uint32_t a) {
    asm volatile("ldmatrix.sync.aligned.m8n8.x2.shared.b16 {%0,%1}, [%2];"
                 : "=r"(r[0]), "=r"(r[1]) : "r"(a));
}
__device__ __forceinline__ void mma_bf16(float c[4], const uint32_t a[4], const uint32_t b[2]) {
    asm volatile("mma.sync.aligned.m16n8k16.row.col.f32.bf16.bf16.f32 "
                 "{%0,%1,%2,%3}, {%4,%5,%6,%7}, {%8,%9}, {%0,%1,%2,%3};"
                 : "+f"(c[0]), "+f"(c[1]), "+f"(c[2]), "+f"(c[3])
                 : "r"(a[0]), "r"(a[1]), "r"(a[2]), "r"(a[3]), "r"(b[0]), "r"(b[1]));
}
__device__ __forceinline__ uint32_t pack_bf16x2(float lo, float hi) {
    uint32_t r;
    asm("cvt.rn.bf16x2.f32 %0, %1, %2;" : "=r"(r) : "f"(hi), "f"(lo));
    return r;
}
__device__ __forceinline__ void cp_async16(uint32_t sdst, const void* gsrc) {
    asm volatile("cp.async.ca.shared.global [%0], [%1], 16;" :: "r"(sdst), "l"(gsrc) : "memory");
}
#define CP_COMMIT() asm volatile("cp.async.commit_group;" ::: "memory")
#define CP_WAIT1()  asm volatile("cp.async.wait_group 1;" ::: "memory")
#define CP_WAIT0()  asm volatile("cp.async.wait_group 0;" ::: "memory")

// pipelined 48B-stride tiles (pv/score/proj)
#define PV_ARR   6144
#define PV_STAGE 24576
#define PV_SMEM  49152
// proj: A(128x48)x2 + B(64x48)x2 per stage
#define PJ_AL   6144
#define PJ_BH   12288
#define PJ_BL   15360
#define PJ_STAGE 18432
#define PJ_SMEM  36864

// =====================================================================
// K0: idx normalize (int32/int64 auto-detect)
// =====================================================================
__global__ void idx_cvt_kernel(const void* __restrict__ raw) {
    const long long* p64 = (const long long*)raw;
    const int*       p32 = (const int*)raw;
    bool is64 = true;
    #pragma unroll
    for (int i = 0; i < 16; i++) {
        long long v = p64[i];
        if (v < 0 || v >= (long long)VOCAB) is64 = false;
    }
    int i = blockIdx.x * blockDim.x + threadIdx.x;
    if (i < NROWS) {
        int v = is64 ? (int)p64[i] : p32[i];
        if (v < 0) v = 0;
        if (v >= VOCAB) v = VOCAB - 1;
        d_idx32[i] = v;
    }
}

// =====================================================================
// K0b: splits (dest resolved device-side — ATS pitfall)
// =====================================================================
__global__ void xsplit_kernel(const float* __restrict__ src, int n4) {
    int i = blockIdx.x * 256 + threadIdx.x;
    if (i >= n4) return;
    float4 v = ((const float4*)src)[i];
    float hx = __bfloat162float(__float2bfloat16(v.x));
    float hy = __bfloat162float(__float2bfloat16(v.y));
    float hz = __bfloat162float(__float2bfloat16(v.z));
    float hw = __bfloat162float(__float2bfloat16(v.w));
    ((uint2*)d_xh)[i] = make_uint2(pack_bf16x2(hx, hy), pack_bf16x2(hz, hw));
    ((uint2*)d_xl)[i] = make_uint2(pack_bf16x2(v.x - hx, v.y - hy), pack_bf16x2(v.z - hz, v.w - hw));
}

__global__ void wsplit_kernel(const float* __restrict__ Wqq, const float* __restrict__ Wk,
                              const float* __restrict__ Wv) {
    int i = blockIdx.x * 256 + threadIdx.x;
    if (i >= NPROJ * CCD / 4) return;
    int row = i >> 8;
    int c4  = i & 255;
    const float* src;
    if (row < 256)      src = Wqq + (size_t)row * CCD;
    else if (row < 288) src = Wk  + (size_t)(row - 256) * CCD;
    else                src = Wv  + (size_t)(row - 288) * CCD;
    float4 v = ((const float4*)src)[c4];
    float hx = __bfloat162float(__float2bfloat16(v.x));
    float hy = __bfloat162float(__float2bfloat16(v.y));
    float hz = __bfloat162float(__float2bfloat16(v.z));
    float hw = __bfloat162float(__float2bfloat16(v.w));
    ((uint2*)d_wh)[i] = make_uint2(pack_bf16x2(hx, hy), pack_bf16x2(hz, hw));
    ((uint2*)d_wl)[i] = make_uint2(pack_bf16x2(v.x - hx, v.y - hy), pack_bf16x2(v.z - hz, v.w - hw));
}

// =====================================================================
// K1: projection GEMM via mma.sync, cp.async 2-stage pipeline (k16)
// =====================================================================
__global__ void __launch_bounds__(256, 2) proj_mma_kernel() {
    extern __shared__ char smem[];
    const int nb = blockIdx.x * 64;
    const int mb = blockIdx.y * 128;
    const uint32_t sb = smem_to_u32(smem);
    const int tid  = threadIdx.x;
    const int lane = tid & 31;
    const int wid  = tid >> 5;
    const int wm = wid & 1;
    const int wn = wid >> 1;
    const int g = lane >> 2, q = lane & 3;

    float acc[4][2][4] = {};

    const int lrow = tid >> 1;          // 0..127
    const int lh   = tid & 1;
    const __nv_bfloat16* gah = d_xh + (size_t)(mb + lrow) * CCD + lh * 8;
    const __nv_bfloat16* gal = d_xl + (size_t)(mb + lrow) * CCD + lh * 8;
    const uint32_t sadst = sb + lrow * 48 + lh * 16;
    const bool bload = tid < 128;
    const __nv_bfloat16* gbh = d_wh + (size_t)(nb + (tid >> 1)) * CCD + lh * 8;
    const __nv_bfloat16* gbl = d_wl + (size_t)(nb + (tid >> 1)) * CCD + lh * 8;
    const uint32_t sbdst = sb + (tid >> 1) * 48 + lh * 16;

    const int nc = CCD / 16;            // 64 chunks

    // prologue
    cp_async16(sadst, gah);
    cp_async16(sadst + PJ_AL, gal);
    if (bload) { cp_async16(sbdst + PJ_BH, gbh); cp_async16(sbdst + PJ_BL, gbl); }
    CP_COMMIT();

    for (int c = 0; c < nc; c++) {
        const uint32_t st = (c & 1) * PJ_STAGE;
        if (c + 1 < nc) {
            const uint32_t st2 = ((c + 1) & 1) * PJ_STAGE;
            const int k1 = (c + 1) * 16;
            cp_async16(sadst + st2, gah + k1);
            cp_async16(sadst + st2 + PJ_AL, gal + k1);
            if (bload) { cp_async16(sbdst + st2 + PJ_BH, gbh + k1); cp_async16(sbdst + st2 + PJ_BL, gbl + k1); }
            CP_COMMIT();
            CP_WAIT1();
        } else {
            CP_WAIT0();
        }
        __syncthreads();
        {
            uint32_t bh[2][2], bl[2][2];
            const int brw = lane & 7;
            const uint32_t bsel = ((lane >> 3) & 1) * 16;
            #pragma unroll
            for (int ni = 0; ni < 2; ni++) {
                uint32_t boff = (wn * 16 + ni * 8 + brw) * 48 + bsel;
                ldsm2(bh[ni], sb + st + PJ_BH + boff);
                ldsm2(bl[ni], sb + st + PJ_BL + boff);
            }
            const int arw = wm * 64 + (lane & 15);
            const uint32_t asel = (lane >> 4) * 16;
            #pragma unroll
            for (int mi = 0; mi < 4; mi++) {
                uint32_t ah[4], al[4];
                uint32_t aoff = (arw + mi * 16) * 48 + asel;
                ldsm4(ah, sb + st + aoff);
                ldsm4(al, sb + st + PJ_AL + aoff);
                #pragma unroll
                for (int ni = 0; ni < 2; ni++) {
                    mma_bf16(acc[mi][ni], ah, bh[ni]);
                    mma_bf16(acc[mi][ni], ah, bl[ni]);
                    mma_bf16(acc[mi][ni], al, bh[ni]);
                }
            }
        }
        __syncthreads();
    }
    #pragma unroll
    for (int mi = 0; mi < 4; mi++) {
        const int r0 = mb + wm * 64 + mi * 16 + g;
        #pragma unroll
        for (int ni = 0; ni < 2; ni++) {
            const int c = nb + wn * 16 + ni * 8 + q * 2;
            *(float2*)&d_proj[(size_t)r0 * NPROJ + c]       = make_float2(acc[mi][ni][0], acc[mi][ni][1]);
            *(float2*)&d_proj[(size_t)(r0 + 8) * NPROJ + c] = make_float2(acc[mi][ni][2], acc[mi][ni][3]);
        }
    }
}

// =====================================================================
// K2a/K2b: low-rank up-projections (unchanged)
// =====================================================================
__global__ void kup_kernel(const float* __restrict__ Wkup, const float* __restrict__ ktab) {
    __shared__ float Ws[32 * 257];
    __shared__ float kds[32][32];
    const int tid = threadIdx.x;
    const int r0 = blockIdx.x * 32;
    for (int i2 = tid; i2 < QD * KVD; i2 += 256) {
        int o = i2 >> 5, d = i2 & 31;
        Ws[d * 257 + o] = Wkup[i2];
    }
    for (int i2 = tid; i2 < 32 * KVD; i2 += 256) {
        int rr = i2 >> 5, d = i2 & 31;
        kds[rr][d] = d_proj[(size_t)(r0 + rr) * NPROJ + 256 + d];
    }
    __syncthreads();
    float a[32];
    #pragma unroll
    for (int rr = 0; rr < 32; rr++) a[rr] = 0.f;
    #pragma unroll
    for (int d = 0; d < 32; d++) {
        float w = Ws[d * 257 + tid];
        #pragma unroll
        for (int rr = 0; rr < 32; rr++) a[rr] += kds[rr][d] * w;
    }
    #pragma unroll
    for (int rr = 0; rr < 32; rr++) {
        int ii = d_idx32[r0 + rr];
        d_kraw[(size_t)(r0 + rr) * QD + tid] = a[rr] * ktab[(size_t)ii * QD + tid];
    }
}

__global__ void vup_kernel(const float* __restrict__ Wvup, const float* __restrict__ vtab) {
    __shared__ float Wtc[32 * 257];
    __shared__ float vds[16][32];
    const int tid = threadIdx.x;
    const int r0 = blockIdx.x * 16;
    for (int i2 = tid; i2 < 16 * KVD; i2 += 256) {
        int rr = i2 >> 5, d = i2 & 31;
        vds[rr][d] = d_proj[(size_t)(r0 + rr) * NPROJ + 288 + d];
    }
    for (int j = 0; j < 4; j++) {
        __syncthreads();
        for (int i2 = tid; i2 < 256 * KVD; i2 += 256) {
            int cl = i2 >> 5, d = i2 & 31;
            Wtc[d * 257 + cl] = Wvup[(size_t)(j * 256 + cl) * KVD + d];
        }
        __syncthreads();
        const int c = j * 256 + tid;
        float a[16];
        #pragma unroll
        for (int rr = 0; rr < 16; rr++) a[rr] = 0.f;
        #pragma unroll
        for (int d = 0; d < 32; d++) {
            float w = Wtc[d * 257 + tid];
            #pragma unroll
            for (int rr = 0; rr < 16; rr++) a[rr] += vds[rr][d] * w;
        }
        #pragma unroll
        for (int rr = 0; rr < 16; rr++) {
            int ii = d_idx32[r0 + rr];
            d_vraw[(size_t)(r0 + rr) * CCD + c] = tanhf(a[rr]) * vtab[(size_t)ii * CCD + c];
        }
    }
}

// =====================================================================
// K3: q/k time-shift + LayerNorm, warp-per-row
// =====================================================================
__global__ void qk_ln_kernel(int which, const float* __restrict__ coef,
                             const float* __restrict__ g, const float* __restrict__ bta) {
    const float* raw; int stride;
    __nv_bfloat16 *oh, *ol;
    if (which == 0) { raw = d_proj; stride = NPROJ; oh = d_qh; ol = d_ql; }
    else            { raw = d_kraw; stride = QD;    oh = d_kh; ol = d_kl; }
    const int r = blockIdx.x * 8 + (threadIdx.x >> 5);
    const int lane = threadIdx.x & 31;
    const int t = r & (TT - 1);
    const float* cur = raw + (size_t)r * stride;
    const float* prv = cur - stride;
    float y[8];
    float s = 0.f, s2 = 0.f;
    #pragma unroll
    for (int j = 0; j < 8; j++) {
        int d = j * 32 + lane;
        float c = cur[d];
        float p = (t > 0) ? prv[d] : 0.f;
        float v = c + (p - c) * coef[d];
        y[j] = v; s += v; s2 += v * v;
    }
    #pragma unroll
    for (int o = 16; o; o >>= 1) {
        s  += __shfl_xor_sync(0xffffffffu, s,  o);
        s2 += __shfl_xor_sync(0xffffffffu, s2, o);
    }
    float mean = s * (1.f / QD);
    float var  = s2 * (1.f / QD) - mean * mean;
    float rstd = rsqrtf(var + 1e-5f);
    #pragma unroll
    for (int j = 0; j < 8; j++) {
        int d = j * 32 + lane;
        float o = (y[j] - mean) * rstd * g[d] + bta[d];
        __nv_bfloat16 hi = __float2bfloat16(o);
        oh[(size_t)r * QD + d] = hi;
        ol[(size_t)r * QD + d] = __float2bfloat16(o - __bfloat162float(hi));
    }
}

// =====================================================================
// K3v: v shift+LN statistics only
// =====================================================================
__global__ void v_stats_kernel(const float* __restrict__ coef) {
    const int r = blockIdx.x * 8 + (threadIdx.x >> 5);
    const int lane = threadIdx.x & 31;
    const int t = r & (TT - 1);
    const float4* cur = (const float4*)(d_vraw + (size_t)r * CCD);
    const float4* prv = cur - CCD / 4;
    const float4* cf  = (const float4*)coef;
    float s = 0.f, s2 = 0.f;
    #pragma unroll
    for (int j = 0; j < 8; j++) {
        int d4 = j * 32 + lane;
        float4 c = cur[d4];
        float4 p = (t > 0) ? prv[d4] : make_float4(0.f, 0.f, 0.f, 0.f);
        float4 w = cf[d4];
        float vx = c.x + (p.x - c.x) * w.x;
        float vy = c.y + (p.y - c.y) * w.y;
        float vz = c.z + (p.z - c.z) * w.z;
        float vw = c.w + (p.w - c.w) * w.w;
        s  += vx + vy + vz + vw;
        s2 += vx * vx + vy * vy + vz * vz + vw * vw;
    }
    #pragma unroll
    for (int o = 16; o; o >>= 1) {
        s  += __shfl_xor_sync(0xffffffffu, s,  o);
        s2 += __shfl_xor_sync(0xffffffffu, s2, o);
    }
    if (lane == 0) {
        float mean = s * (1.f / CCD);
        float var  = s2 * (1.f / CCD) - mean * mean;
        d_vmean[r] = mean;
        d_vrstd[r] = rsqrtf(var + 1e-5f);
    }
}

// =====================================================================
// K3b: fused shift+LN+transpose+split: vraw -> Vt bf16 hi/lo
// =====================================================================
__global__ void vt_cvt_kernel(const float* __restrict__ xv, const float* __restrict__ gv,
                              const float* __restrict__ bv) {
    __shared__ float ts[33][33];
    const int c0 = blockIdx.x * 32;
    const int r0 = blockIdx.y * 32;
    for (int i2 = threadIdx.x; i2 < 33 * 32; i2 += 256) {
        int rr = i2 >> 5, cc = i2 & 31;
        int grow = r0 - 1 + rr;
        if (grow < 0) grow = 0;
        ts[rr][cc] = d_vraw[(size_t)grow * CCD + c0 + cc];
    }
    __syncthreads();
    const int lx = threadIdx.x & 31;
    const int ly = threadIdx.x >> 5;
    const int bz = r0 >> 11;
    const int t0 = r0 & (TT - 1);
    const int t  = t0 + lx;
    const int r  = r0 + lx;
    const float mean = d_vmean[r];
    const float rstd = d_vrstd[r];
    #pragma unroll
    for (int i = 0; i < 4; i++) {
        int cc = ly + i * 8;
        int c  = c0 + cc;
        float curv = ts[lx + 1][cc];
        float prev = (t > 0) ? ts[lx][cc] : 0.f;
        float y = curv + (prev - curv) * xv[c];
        float v = (y - mean) * rstd * gv[c] + bv[c];
        size_t o = (size_t)(bz * CCD + c) * TT + t;
        __nv_bfloat16 hi = __float2bfloat16(v);
        d_vth[o] = hi;
        d_vtl[o] = __float2bfloat16(v - __bfloat162float(hi));
    }
}

// =====================================================================
// K4a: score via mma.sync, cp.async 2-stage pipeline (k16, pv pattern)
// =====================================================================
__global__ void __launch_bounds__(256, 2) score_mma_kernel() {
    extern __shared__ char smem[];
    const int tj = blockIdx.x, ti = 15 - blockIdx.y, b = blockIdx.z;
    if (tj > ti) return;
    const uint32_t sb = smem_to_u32(smem);
    const int tid  = threadIdx.x;
    const int lane = tid & 31;
    const int wid  = tid >> 5;
    const int wm = wid & 1;
    const int wn = wid >> 1;
    const int g = lane >> 2, q = lane & 3;

    float acc[4][4][4] = {};

    const int lrow = tid >> 1;
    const int lh   = tid & 1;
    const size_t qoff = (size_t)(b * TT + ti * 128 + lrow) * QD + lh * 8;
    const size_t koff = (size_t)(b * TT + tj * 128 + lrow) * QD + lh * 8;
    const __nv_bfloat16* gsrc[4] = { d_qh + qoff, d_ql + qoff, d_kh + koff, d_kl + koff };
    const uint32_t sldst = sb + lrow * 48 + lh * 16;

    const int nc = QD / 16;             // 16 chunks

    #pragma unroll
    for (int a = 0; a < 4; a++) cp_async16(sldst + a * PV_ARR, gsrc[a]);
    CP_COMMIT();

    for (int c = 0; c < nc; c++) {
        const uint32_t st = (c & 1) * PV_STAGE;
        if (c + 1 < nc) {
            const uint32_t st2 = ((c + 1) & 1) * PV_STAGE;
            const int k1 = (c + 1) * 16;
            #pragma unroll
            for (int a = 0; a < 4; a++) cp_async16(sldst + st2 + a * PV_ARR, gsrc[a] + k1);
            CP_COMMIT();
            CP_WAIT1();
        } else {
            CP_WAIT0();
        }
        __syncthreads();
        {
            uint32_t bh[4][2], bl[4][2];
            const int brow = lane & 7;
            const uint32_t bsel = ((lane >> 3) & 1) * 16;
            #pragma unroll
            for (int ni = 0; ni < 4; ni++) {
                uint32_t boff = (wn * 32 + ni * 8 + brow) * 48 + bsel;
                ldsm2(bh[ni], sb + st + 2 * PV_ARR + boff);
                ldsm2(bl[ni], sb + st + 3 * PV_ARR + boff);
            }
            const int arow = wm * 64 + (lane & 15);
            const uint32_t asel = (lane >> 4) * 16;
            #pragma unroll
            for (int mi = 0; mi < 4; mi++) {
                uint32_t ah[4], al[4];
                uint32_t aoff = (arow + mi * 16) * 48 + asel;
                ldsm4(ah, sb + st + aoff);
                ldsm4(al, sb + st + 1 * PV_ARR + aoff);
                #pragma unroll
                for (int ni = 0; ni < 4; ni++) {
                    mma_bf16(acc[mi][ni], ah, bh[ni]);
                    mma_bf16(acc[mi][ni], ah, bl[ni]);
                    mma_bf16(acc[mi][ni], al, bh[ni]);
                }
            }
        }
        __syncthreads();
    }

    #pragma unroll
    for (int mi = 0; mi < 4; mi++) {
        const int tg0 = ti * 128 + wm * 64 + mi * 16 + g;
        const int tg1 = tg0 + 8;
        float ps0 = 0.f, ps1 = 0.f;
        #pragma unroll
        for (int ni = 0; ni < 4; ni++) {
            const int sg = tj * 128 + wn * 32 + ni * 8 + q * 2;
            #pragma unroll
            for (int e = 0; e < 4; e++) {
                const int col = sg + (e & 1);
                const int row = (e < 2) ? tg0 : tg1;
                float p = 0.f;
                if (col <= row) {
                    float d = acc[mi][ni][e];
                    float u = __expf(d * (1.f / 512.f));
                    float th = __fdividef(u - 1.f, u + 1.f);
                    p = __expf(64.f * th);
                }
                acc[mi][ni][e] = p;
                if (e < 2) ps0 += p; else ps1 += p;
            }
        }
        ps0 += __shfl_xor_sync(0xffffffffu, ps0, 1);
        ps0 += __shfl_xor_sync(0xffffffffu, ps0, 2);
        ps1 += __shfl_xor_sync(0xffffffffu, ps1, 1);
        ps1 += __shfl_xor_sync(0xffffffffu, ps1, 2);
        if (q == 0) {
            d_psum[(size_t)(b * TT + tg0) * 64 + tj * 4 + wn] = ps0;
            d_psum[(size_t)(b * TT + tg1) * 64 + tj * 4 + wn] = ps1;
        }
    }

    uint32_t* stg = (uint32_t*)smem;
    const int cpair = wn * 16 + q;
    for (int pass = 0; pass < 2; pass++) {
        __syncthreads();
        #pragma unroll
        for (int mi = 0; mi < 4; mi++) {
            const int r0 = wm * 64 + mi * 16 + g;
            #pragma unroll
            for (int ni = 0; ni < 4; ni++) {
                float v0 = acc[mi][ni][0], v1 = acc[mi][ni][1];
                float v2 = acc[mi][ni][2], v3 = acc[mi][ni][3];
                if (pass == 1) {
                    v0 -= __bfloat162float(__float2bfloat16(v0));
                    v1 -= __bfloat162float(__float2bfloat16(v1));
                    v2 -= __bfloat162float(__float2bfloat16(v2));
                    v3 -= __bfloat162float(__float2bfloat16(v3));
                }
                stg[r0 * 68 + cpair + ni * 4]       = pack_bf16x2(v0, v1);
                stg[(r0 + 8) * 68 + cpair + ni * 4] = pack_bf16x2(v2, v3);
            }
        }
        __syncthreads();
        __nv_bfloat16* gbase = (pass == 0) ? d_ph : d_pl;
        const int srow = tid >> 1;
        const int c0 = (tid & 1) * 32;
        uint4* gp = (uint4*)(gbase + (size_t)(b * TT + ti * 128 + srow) * TT
                             + (size_t)tj * 128 + (tid & 1) * 64);
        const uint4* sp = (const uint4*)(stg + srow * 68 + c0);
        #pragma unroll
        for (int i = 0; i < 8; i++) gp[i] = sp[i];
    }
}

// =====================================================================
// K4c: rowsum from 32-col stripe partials
// =====================================================================
__global__ void psum_reduce_kernel() {
    int r = blockIdx.x * 256 + threadIdx.x;
    int t = r & (TT - 1);
    int n = (t >> 5) + 1;
    const float* p = d_psum + (size_t)r * 64;
    float s = 0.f;
    for (int j = 0; j < n; j++) s += p[j];
    d_rowsum[r] = s;
}

// =====================================================================
// K4b: PV via mma.sync, cp.async 2-stage (unchanged from passing R10)
// =====================================================================
__global__ void __launch_bounds__(256, 2) pv_mma_kernel(float* __restrict__ out) {
    extern __shared__ char smem[];
    const int cb = blockIdx.x, ti = 15 - blockIdx.y, b = blockIdx.z;
    const uint32_t sb = smem_to_u32(smem);
    const int tid  = threadIdx.x;
    const int lane = tid & 31;
    const int wid  = tid >> 5;
    const int wm = wid & 1;
    const int wn = wid >> 1;
    const int g = lane >> 2, q = lane & 3;

    float acc[4][4][4] = {};

    const int lrow = tid >> 1;
    const int lh   = tid & 1;
    const size_t poff = (size_t)(b * TT + ti * 128 + lrow) * TT + lh * 8;
    const size_t voff = (size_t)(b * CCD + cb * 128 + lrow) * TT + lh * 8;
    const __nv_bfloat16* gsrc[4] = { d_ph + poff, d_pl + poff, d_vth + voff, d_vtl + voff };
    const uint32_t sldst = sb + lrow * 48 + lh * 16;

    const int nc = (ti + 1) * 8;

    #pragma unroll
    for (int a = 0; a < 4; a++) cp_async16(sldst + a * PV_ARR, gsrc[a]);
    CP_COMMIT();

    for (int c = 0; c < nc; c++) {
        const uint32_t st = (c & 1) * PV_STAGE;
        if (c + 1 < nc) {
            const uint32_t st2 = ((c + 1) & 1) * PV_STAGE;
            const int k1 = (c + 1) * 16;
            #pragma unroll
            for (int a = 0; a < 4; a++) cp_async16(sldst + st2 + a * PV_ARR, gsrc[a] + k1);
            CP_COMMIT();
            CP_WAIT1();
        } else {
            CP_WAIT0();
        }
        __syncthreads();
        {
            uint32_t bh[4][2], bl[4][2];
            const int brow = lane & 7;
            const uint32_t bsel = ((lane >> 3) & 1) * 16;
            #pragma unroll
            for (int ni = 0; ni < 4; ni++) {
                uint32_t boff = (wn * 32 + ni * 8 + brow) * 48 + bsel;
                ldsm2(bh[ni], sb + st + 2 * PV_ARR + boff);
                ldsm2(bl[ni], sb + st + 3 * PV_ARR + boff);
            }
            const int arow = wm * 64 + (lane & 15);
            const uint32_t asel = (lane >> 4) * 16;
            #pragma unroll
            for (int mi = 0; mi < 4; mi++) {
                uint32_t ah[4], al[4];
                uint32_t aoff = (arow + mi * 16) * 48 + asel;
                ldsm4(ah, sb + st + aoff);
                ldsm4(al, sb + st + 1 * PV_ARR + aoff);
                #pragma unroll
                for (int ni = 0; ni < 4; ni++) {
                    mma_bf16(acc[mi][ni], ah, bh[ni]);
                    mma_bf16(acc[mi][ni], ah, bl[ni]);
                    mma_bf16(acc[mi][ni], al, bh[ni]);
                }
            }
        }
        __syncthreads();
    }

    float inv0[4], inv1[4];
    #pragma unroll
    for (int mi = 0; mi < 4; mi++) {
        int rg = b * TT + ti * 128 + wm * 64 + mi * 16 + g;
        inv0[mi] = 1.f / d_rowsum[rg];
        inv1[mi] = 1.f / d_rowsum[rg + 8];
    }

    float* stg = (float*)smem;
    for (int h = 0; h < 2; h++) {
        __syncthreads();
        if ((wn >> 1) == h) {
            const int cbase = (wn & 1) * 32 + q * 2;
            #pragma unroll
            for (int mi = 0; mi < 4; mi++) {
                const int r0 = wm * 64 + mi * 16 + g;
                #pragma unroll
                for (int ni = 0; ni < 4; ni++) {
                    const int c = cbase + ni * 8;
                    stg[r0 * 68 + c]           = acc[mi][ni][0] * inv0[mi];
                    stg[r0 * 68 + c + 1]       = acc[mi][ni][1] * inv0[mi];
                    stg[(r0 + 8) * 68 + c]     = acc[mi][ni][2] * inv1[mi];
                    stg[(r0 + 8) * 68 + c + 1] = acc[mi][ni][3] * inv1[mi];
                }
            }
        }
        __syncthreads();
        const int srow = tid >> 1;
        const int c0 = (tid & 1) * 32;
        float4* gp = (float4*)(out + (size_t)(b * TT + ti * 128 + srow) * CCD
                               + (size_t)cb * 128 + h * 64 + c0);
        const float4* sp = (const float4*)(stg + srow * 68 + c0);
        #pragma unroll
        for (int i = 0; i < 8; i++) gp[i] = sp[i];
    }
}

// =====================================================================
extern "C" void kernel_launch(void* const* d_in, const int* in_sizes, int n_in,
                              void* d_out, int out_size) {
    const float* x     = (const float*)d_in[0];
    const void*  idx   = d_in[1];
    const float* Wqq   = (const float*)d_in[2];
    const float* Wk    = (const float*)d_in[3];
    const float* Wkup  = (const float*)d_in[4];
    const float* Wv    = (const float*)d_in[5];
    const float* Wvup  = (const float*)d_in[6];
    const float* ktab  = (const float*)d_in[7];
    const float* vtab  = (const float*)d_in[8];
    const float* xq    = (const float*)d_in[9];
    const float* xk    = (const float*)d_in[10];
    const float* xv    = (const float*)d_in[11];
    const float* gq    = (const float*)d_in[12];
    const float* bq    = (const float*)d_in[13];
    const float* gk    = (const float*)d_in[14];
    const float* bk    = (const float*)d_in[15];
    const float* gv    = (const float*)d_in[16];
    const float* bv    = (const float*)d_in[17];
    float* out = (float*)d_out;

    idx_cvt_kernel<<<NROWS / 256, 256>>>(idx);
    xsplit_kernel<<<NROWS * CCD / 4 / 256, 256>>>(x, NROWS * CCD / 4);
    wsplit_kernel<<<NPROJ * CCD / 4 / 256, 256>>>(Wqq, Wk, Wv);
    proj_mma_kernel<<<dim3(5, 64), 256, PJ_SMEM>>>();
    kup_kernel<<<NROWS / 32, 256>>>(Wkup, ktab);
    vup_kernel<<<NROWS / 16, 256>>>(Wvup, vtab);
    qk_ln_kernel<<<NROWS / 8, 256>>>(0, xq, gq, bq);
    qk_ln_kernel<<<NROWS / 8, 256>>>(1, xk, gk, bk);
    v_stats_kernel<<<NROWS / 8, 256>>>(xv);
    vt_cvt_kernel<<<dim3(CCD / 32, NROWS / 32), 256>>>(xv, gv, bv);
    score_mma_kernel<<<dim3(16, 16, 4), 256, PV_SMEM>>>();
    psum_reduce_kernel<<<NROWS / 256, 256>>>();
    pv_mma_kernel<<<dim3(8, 16, 4), 256, PV_SMEM>>>(out);
}